// round 4
// baseline (speedup 1.0000x reference)
#include <cuda_runtime.h>

#define NN 100000
#define NE 800000
#define HD 128
#define NG 500
#define SCAN_B 1024
#define NBLK ((NN + SCAN_B - 1) / SCAN_B)   // 98

// ---------------- scratch (device globals; no allocation) ----------------
__device__ float g_x [NN * HD];   // ping
__device__ float g_y [NN * HD];   // pong
__device__ float g_xw[NN * HD];   // x @ W
__device__ float g_dinv[NN];
__device__ int   g_cnt[NN];
__device__ int   g_rowptr[NN + 1];
__device__ int   g_cursor[NN];
__device__ int   g_csr[NE];       // src node per (dst-sorted) live edge
__device__ int   g_bsum[128];
__device__ int   g_mask_i32;      // 1 if edge_mask serialized as int32

// TF32 round (matches GPU tf32 matmul operand rounding)
__device__ __forceinline__ float tf32r(float x) {
    float r;
    asm("cvt.rna.tf32.f32 %0, %1;" : "=f"(r) : "f"(x));
    return r;
}
__device__ __forceinline__ float4 tf32r4(float4 v) {
    return make_float4(tf32r(v.x), tf32r(v.y), tf32r(v.z), tf32r(v.w));
}

// ---------------- mask dtype detection ----------------
// If mask is int32 of {0,1}, every byte at offset %4 != 0 is zero.
// If mask is uint8 bools (~50% ones), many such bytes are nonzero.
__global__ void k_detect(const unsigned char* __restrict__ m) {
    __shared__ int any;
    if (threadIdx.x == 0) any = 0;
    __syncthreads();
    int local = 0;
    for (int i = threadIdx.x; i < 65536; i += blockDim.x)
        if ((i & 3) && m[i]) local = 1;
    if (local) any = 1;                  // benign race
    __syncthreads();
    if (threadIdx.x == 0) g_mask_i32 = (any == 0);
}

__device__ __forceinline__ bool mlive(const unsigned char* m, int e, int is32) {
    if (is32) return ((const int*)m)[e] != 0;
    return m[e] != 0;
}

// ---------------- embedding: x = z_table[z] ----------------
__global__ void k_embed(const int* __restrict__ z,
                        const float* __restrict__ zt) {
    int idx = blockIdx.x * blockDim.x + threadIdx.x;   // one float4 each
    if (idx >= NN * (HD / 4)) return;
    int node = idx >> 5;          // /32
    int c    = idx & 31;
    int zz   = z[node];
    ((float4*)g_x)[idx] = ((const float4*)zt)[zz * 32 + c];
}

// ---------------- CSR build ----------------
__global__ void k_zero_cnt() {
    int i = blockIdx.x * blockDim.x + threadIdx.x;
    if (i < NN) g_cnt[i] = 0;
}

__global__ void k_count(const int* __restrict__ dst,
                        const unsigned char* __restrict__ mask) {
    int e = blockIdx.x * blockDim.x + threadIdx.x;
    if (e >= NE) return;
    if (mlive(mask, e, g_mask_i32)) atomicAdd(&g_cnt[dst[e]], 1);
}

__global__ void k_dinv() {
    int i = blockIdx.x * blockDim.x + threadIdx.x;
    if (i < NN) g_dinv[i] = rsqrtf((float)g_cnt[i] + 1.0f);
}

__global__ void k_scan1() {
    __shared__ int s[SCAN_B];
    int i = blockIdx.x * SCAN_B + threadIdx.x;
    int v = (i < NN) ? g_cnt[i] : 0;
    s[threadIdx.x] = v;
    __syncthreads();
    for (int off = 1; off < SCAN_B; off <<= 1) {
        int t = (threadIdx.x >= off) ? s[threadIdx.x - off] : 0;
        __syncthreads();
        s[threadIdx.x] += t;
        __syncthreads();
    }
    if (i < NN) g_rowptr[i] = s[threadIdx.x] - v;   // block-local exclusive
    if (threadIdx.x == SCAN_B - 1) g_bsum[blockIdx.x] = s[SCAN_B - 1];
}

__global__ void k_scan2() {   // single block of 128 threads
    __shared__ int s[128];
    int t = threadIdx.x;
    int v = (t < NBLK) ? g_bsum[t] : 0;
    s[t] = v;
    __syncthreads();
    for (int off = 1; off < 128; off <<= 1) {
        int tt = (t >= off) ? s[t - off] : 0;
        __syncthreads();
        s[t] += tt;
        __syncthreads();
    }
    if (t < NBLK) g_bsum[t] = s[t] - v;             // exclusive block offsets
    if (t == NBLK - 1) g_rowptr[NN] = s[t];         // total live edges
}

__global__ void k_scan3() {
    int i = blockIdx.x * blockDim.x + threadIdx.x;
    if (i >= NN) return;
    int r = g_rowptr[i] + g_bsum[i / SCAN_B];
    g_rowptr[i] = r;
    g_cursor[i] = r;
}

__global__ void k_fill(const int* __restrict__ src,
                       const int* __restrict__ dst,
                       const unsigned char* __restrict__ mask) {
    int e = blockIdx.x * blockDim.x + threadIdx.x;
    if (e >= NE) return;
    if (mlive(mask, e, g_mask_i32)) {
        int pos = atomicAdd(&g_cursor[dst[e]], 1);
        g_csr[pos] = src[e];
    }
}

// ---------------- GEMM: g_xw = tf32(A)[N,128] @ tf32(W)[128,128] ----------------
// block: 32 rows x 64 cols, 256 threads, thread tile 2x4, smem = 48KB exactly
#define BM 32
#define BN 64
__global__ __launch_bounds__(256)
void k_gemm(const float* __restrict__ A, const float* __restrict__ W) {
    __shared__ float As[BM][HD];      // 16 KB
    __shared__ float Ws[HD][BN];      // 32 KB
    int rowbase = blockIdx.x * BM;
    int colbase = blockIdx.y * BN;
    int t = threadIdx.x;

    const float4* A4 = (const float4*)(A + rowbase * HD);
    float4* As4 = (float4*)As;
    #pragma unroll
    for (int i = t; i < BM * HD / 4; i += 256) As4[i] = tf32r4(A4[i]);

    #pragma unroll
    for (int q = t; q < HD * (BN / 4); q += 256) {
        int k = q / (BN / 4), c = q % (BN / 4);
        ((float4*)Ws)[q] = tf32r4(*(const float4*)(W + k * HD + colbase + c * 4));
    }
    __syncthreads();

    int tc = t & 15;            // 16 col groups of 4
    int tr = t >> 4;            // 16 row pairs
    int r0 = tr * 2, r1 = r0 + 1;
    float acc00 = 0.f, acc01 = 0.f, acc02 = 0.f, acc03 = 0.f;
    float acc10 = 0.f, acc11 = 0.f, acc12 = 0.f, acc13 = 0.f;

    #pragma unroll 8
    for (int k = 0; k < HD; k++) {
        float a0 = As[r0][k];
        float a1 = As[r1][k];
        float4 w = ((const float4*)&Ws[k][0])[tc];
        acc00 += a0 * w.x; acc01 += a0 * w.y; acc02 += a0 * w.z; acc03 += a0 * w.w;
        acc10 += a1 * w.x; acc11 += a1 * w.y; acc12 += a1 * w.z; acc13 += a1 * w.w;
    }
    float4 v0 = make_float4(acc00, acc01, acc02, acc03);
    float4 v1 = make_float4(acc10, acc11, acc12, acc13);
    *(float4*)(g_xw + (size_t)(rowbase + r0) * HD + colbase + tc * 4) = v0;
    *(float4*)(g_xw + (size_t)(rowbase + r1) * HD + colbase + tc * 4) = v1;
}

// ---------------- conv aggregation (gather, no atomics, exact fp32) ----------------
// 1 warp per dst node, each lane owns 4 features (float4)
__global__ void k_gather(const float* __restrict__ bias,
                         float* __restrict__ out, int do_relu) {
    int gtid = blockIdx.x * blockDim.x + threadIdx.x;
    int node = gtid >> 5;
    int lane = gtid & 31;
    if (node >= NN) return;

    const float4* xw4 = (const float4*)g_xw;
    float s  = g_dinv[node];
    float ss = s * s;
    float4 a = xw4[(size_t)node * 32 + lane];
    float4 acc = make_float4(ss * a.x, ss * a.y, ss * a.z, ss * a.w);

    int e0 = g_rowptr[node], e1 = g_rowptr[node + 1];
    for (int e = e0; e < e1; e++) {
        int j = g_csr[e];
        float c = s * g_dinv[j];
        float4 v = xw4[(size_t)j * 32 + lane];
        acc.x += c * v.x; acc.y += c * v.y; acc.z += c * v.z; acc.w += c * v.w;
    }
    float4 bb = ((const float4*)bias)[lane];
    acc.x += bb.x; acc.y += bb.y; acc.z += bb.z; acc.w += bb.w;
    if (do_relu) {
        acc.x = fmaxf(acc.x, 0.f); acc.y = fmaxf(acc.y, 0.f);
        acc.z = fmaxf(acc.z, 0.f); acc.w = fmaxf(acc.w, 0.f);
    }
    ((float4*)out)[(size_t)node * 32 + lane] = acc;
}

// ---------------- pooling + MLP head (matmuls in tf32) ----------------
__global__ void k_pool(const float* __restrict__ x,
                       const float* __restrict__ l1w,
                       const float* __restrict__ l1b,
                       const float* __restrict__ l2w,
                       const float* __restrict__ l2b,
                       float* __restrict__ out) {
    __shared__ float h[HD];
    __shared__ float red[4];
    int g = blockIdx.x, t = threadIdx.x;
    long long n0 = (long long)g * 200;
    // hadamard product exact fp32, then tf32-round as matmul operand
    h[t] = tf32r(x[n0 * HD + t] * x[(n0 + 1) * HD + t]);
    __syncthreads();
    float acc = l1b[t];
    #pragma unroll 16
    for (int i = 0; i < HD; i++) acc += h[i] * tf32r(l1w[i * HD + t]);
    acc = fmaxf(acc, 0.f);
    float p = tf32r(acc) * tf32r(l2w[t]);
    #pragma unroll
    for (int o = 16; o; o >>= 1) p += __shfl_xor_sync(0xffffffffu, p, o);
    if ((t & 31) == 0) red[t >> 5] = p;
    __syncthreads();
    if (t == 0) out[g] = red[0] + red[1] + red[2] + red[3] + l2b[0];
}

// ---------------- launch ----------------
extern "C" void kernel_launch(void* const* d_in, const int* in_sizes, int n_in,
                              void* d_out, int out_size) {
    const int*           z    = (const int*)d_in[0];
    const int*           ei   = (const int*)d_in[1];
    const unsigned char* mask = (const unsigned char*)d_in[3];
    const float* zt  = (const float*)d_in[4];
    const float* W0  = (const float*)d_in[5];
    const float* b0  = (const float*)d_in[6];
    const float* W1  = (const float*)d_in[7];
    const float* b1  = (const float*)d_in[8];
    const float* W2  = (const float*)d_in[9];
    const float* b2  = (const float*)d_in[10];
    const float* l1w = (const float*)d_in[11];
    const float* l1b = (const float*)d_in[12];
    const float* l2w = (const float*)d_in[13];
    const float* l2b = (const float*)d_in[14];
    float* out = (float*)d_out;

    const int* src = ei;
    const int* dst = ei + NE;

    float *px = nullptr, *py = nullptr;
    cudaGetSymbolAddress((void**)&px, g_x);
    cudaGetSymbolAddress((void**)&py, g_y);

    // mask dtype sniff (int32 bool vs uint8 bool)
    k_detect<<<1, 256>>>(mask);

    // embedding
    k_embed<<<(NN * 32 + 255) / 256, 256>>>(z, zt);

    // CSR + dinv (shared by all 3 layers)
    k_zero_cnt<<<(NN + 255) / 256, 256>>>();
    k_count<<<(NE + 255) / 256, 256>>>(dst, mask);
    k_dinv<<<(NN + 255) / 256, 256>>>();
    k_scan1<<<NBLK, SCAN_B>>>();
    k_scan2<<<1, 128>>>();
    k_scan3<<<(NN + 255) / 256, 256>>>();
    k_fill<<<(NE + 255) / 256, 256>>>(src, dst, mask);

    dim3 ggrid(NN / BM, HD / BN);   // (3125, 2)

    // layer 0: x -> y (relu)
    k_gemm<<<ggrid, 256>>>(px, W0);
    k_gather<<<(NN * 32 + 255) / 256, 256>>>(b0, py, 1);
    // layer 1: y -> x (relu)
    k_gemm<<<ggrid, 256>>>(py, W1);
    k_gather<<<(NN * 32 + 255) / 256, 256>>>(b1, px, 1);
    // layer 2: x -> y (no relu)
    k_gemm<<<ggrid, 256>>>(px, W2);
    k_gather<<<(NN * 32 + 255) / 256, 256>>>(b2, py, 0);

    // pool + MLP
    k_pool<<<NG, HD>>>(py, l1w, l1b, l2w, l2b, out);
}

// round 5
// speedup vs baseline: 1.2811x; 1.2811x over previous
#include <cuda_runtime.h>
#include <cstdint>

#define NN 100000
#define NE 800000
#define HD 128
#define NG 500
#define SCAN_B 1024
#define NBLK ((NN + SCAN_B - 1) / SCAN_B)   // 98
#define PAD 132                              // A-tile row stride (floats)

// ---------------- scratch (device globals; no allocation) ----------------
__device__ float g_x [NN * HD];   // ping
__device__ float g_y [NN * HD];   // pong
__device__ float g_xw[NN * HD];   // x @ W
__device__ float g_wf[3 * 16384]; // pre-packed W B-fragments (3 layers)
__device__ float g_dinv[NN];
__device__ int   g_cnt[NN];
__device__ int   g_rowptr[NN + 1];
__device__ int   g_cursor[NN];
__device__ int   g_csr[NE];       // src node per (dst-sorted) live edge
__device__ int   g_bsum[128];
__device__ int   g_mask_i32;      // 1 if edge_mask serialized as int32

// TF32 round (matches GPU tf32 matmul operand rounding)
__device__ __forceinline__ float tf32r(float x) {
    float r;
    asm("cvt.rna.tf32.f32 %0, %1;" : "=f"(r) : "f"(x));
    return r;
}
__device__ __forceinline__ float4 tf32r4(float4 v) {
    return make_float4(tf32r(v.x), tf32r(v.y), tf32r(v.z), tf32r(v.w));
}

__device__ __forceinline__ void mma_tf32(float4& c,
    uint32_t a0, uint32_t a1, uint32_t a2, uint32_t a3,
    uint32_t b0, uint32_t b1) {
    asm volatile(
        "mma.sync.aligned.m16n8k8.row.col.f32.tf32.tf32.f32 "
        "{%0,%1,%2,%3}, {%4,%5,%6,%7}, {%8,%9}, {%0,%1,%2,%3};"
        : "+f"(c.x), "+f"(c.y), "+f"(c.z), "+f"(c.w)
        : "r"(a0), "r"(a1), "r"(a2), "r"(a3), "r"(b0), "r"(b1));
}

// ---------------- mask dtype detection ----------------
__global__ void k_detect(const unsigned char* __restrict__ m) {
    __shared__ int any;
    if (threadIdx.x == 0) any = 0;
    __syncthreads();
    int local = 0;
    for (int i = threadIdx.x; i < 65536; i += blockDim.x)
        if ((i & 3) && m[i]) local = 1;
    if (local) any = 1;                  // benign race
    __syncthreads();
    if (threadIdx.x == 0) g_mask_i32 = (any == 0);
}

__device__ __forceinline__ bool mlive(const unsigned char* m, int e, int is32) {
    if (is32) return ((const int*)m)[e] != 0;
    return m[e] != 0;
}

// ---------------- embedding: x = z_table[z] ----------------
__global__ void k_embed(const int* __restrict__ z,
                        const float* __restrict__ zt) {
    int idx = blockIdx.x * blockDim.x + threadIdx.x;   // one float4 each
    if (idx >= NN * (HD / 4)) return;
    int node = idx >> 5;          // /32
    int c    = idx & 31;
    int zz   = z[node];
    ((float4*)g_x)[idx] = ((const float4*)zt)[zz * 32 + c];
}

// ---------------- CSR build ----------------
__global__ void k_zero_cnt() {
    int i = blockIdx.x * blockDim.x + threadIdx.x;
    if (i < NN) g_cnt[i] = 0;
}

__global__ void k_count(const int* __restrict__ dst,
                        const unsigned char* __restrict__ mask) {
    int e = blockIdx.x * blockDim.x + threadIdx.x;
    if (e >= NE) return;
    if (mlive(mask, e, g_mask_i32)) atomicAdd(&g_cnt[dst[e]], 1);
}

__global__ void k_dinv() {
    int i = blockIdx.x * blockDim.x + threadIdx.x;
    if (i < NN) g_dinv[i] = rsqrtf((float)g_cnt[i] + 1.0f);
}

__global__ void k_scan1() {
    __shared__ int s[SCAN_B];
    int i = blockIdx.x * SCAN_B + threadIdx.x;
    int v = (i < NN) ? g_cnt[i] : 0;
    s[threadIdx.x] = v;
    __syncthreads();
    for (int off = 1; off < SCAN_B; off <<= 1) {
        int t = (threadIdx.x >= off) ? s[threadIdx.x - off] : 0;
        __syncthreads();
        s[threadIdx.x] += t;
        __syncthreads();
    }
    if (i < NN) g_rowptr[i] = s[threadIdx.x] - v;   // block-local exclusive
    if (threadIdx.x == SCAN_B - 1) g_bsum[blockIdx.x] = s[SCAN_B - 1];
}

__global__ void k_scan2() {   // single block of 128 threads
    __shared__ int s[128];
    int t = threadIdx.x;
    int v = (t < NBLK) ? g_bsum[t] : 0;
    s[t] = v;
    __syncthreads();
    for (int off = 1; off < 128; off <<= 1) {
        int tt = (t >= off) ? s[t - off] : 0;
        __syncthreads();
        s[t] += tt;
        __syncthreads();
    }
    if (t < NBLK) g_bsum[t] = s[t] - v;             // exclusive block offsets
    if (t == NBLK - 1) g_rowptr[NN] = s[t];         // total live edges
}

__global__ void k_scan3() {
    int i = blockIdx.x * blockDim.x + threadIdx.x;
    if (i >= NN) return;
    int r = g_rowptr[i] + g_bsum[i / SCAN_B];
    g_rowptr[i] = r;
    g_cursor[i] = r;
}

__global__ void k_fill(const int* __restrict__ src,
                       const int* __restrict__ dst,
                       const unsigned char* __restrict__ mask) {
    int e = blockIdx.x * blockDim.x + threadIdx.x;
    if (e >= NE) return;
    if (mlive(mask, e, g_mask_i32)) {
        int pos = atomicAdd(&g_cursor[dst[e]], 1);
        g_csr[pos] = src[e];
    }
}

// ---------------- W fragment packing (once per launch, all 3 layers) ----------
// B frag (k8n8, col-major operand) for m16n8k8: b0 = W[k0+lane%4][n0+lane/4],
// b1 = W[k0+4+lane%4][n0+lane/4]. Stored as float2 at [(nt*16+kt)*32+lane].
__global__ void kw_pack(const float* __restrict__ W0,
                        const float* __restrict__ W1,
                        const float* __restrict__ W2) {
    const float* W = (blockIdx.x == 0) ? W0 : (blockIdx.x == 1) ? W1 : W2;
    float2* out = (float2*)(g_wf + blockIdx.x * 16384);
    for (int idx = threadIdx.x; idx < 8192; idx += blockDim.x) {
        int lane = idx & 31, kt = (idx >> 5) & 15, nt = idx >> 9;
        int k = kt * 8 + (lane & 3);
        int n = nt * 8 + (lane >> 2);
        float b0 = tf32r(W[k * HD + n]);
        float b1 = tf32r(W[(k + 4) * HD + n]);
        out[idx] = make_float2(b0, b1);
    }
}

// ---------------- tensor-core GEMM: g_xw = tf32(A)[N,128] @ tf32(W)[128,128] --
// 256 threads / 8 warps. Warp grid 4 (rows) x 2 (cols). Per warp: 32 rows x 64
// cols = 2 m-tiles x 8 n-tiles of m16n8, K = 128 in 16 k8 steps.
__global__ __launch_bounds__(256)
void k_gemm_tc(const float* __restrict__ A, int layer) {
    extern __shared__ float sm[];
    float* As = sm;                   // 128 x PAD floats
    float* Wf = sm + 128 * PAD;       // 16384 floats

    int rb = blockIdx.x * 128;
    int t = threadIdx.x;

    // stage A tile (tf32-rounded, zero-fill past NN)
    for (int i = t; i < 128 * 32; i += 256) {
        int row = i >> 5, c4 = i & 31;
        float4 v = make_float4(0.f, 0.f, 0.f, 0.f);
        if (rb + row < NN) v = ((const float4*)A)[(size_t)(rb + row) * 32 + c4];
        *(float4*)&As[row * PAD + c4 * 4] = tf32r4(v);
    }
    // stage packed W
    const float4* wsrc = (const float4*)(g_wf + layer * 16384);
    for (int i = t; i < 4096; i += 256) ((float4*)Wf)[i] = wsrc[i];
    __syncthreads();

    int wid = t >> 5, lane = t & 31;
    int rg = wid & 3;          // row group (32 rows each)
    int cg = wid >> 2;         // col group (64 cols each)
    int row_l = lane >> 2;     // 0..7
    int kq = lane & 3;         // 0..3

    float4 acc[2][8];
    #pragma unroll
    for (int mt = 0; mt < 2; mt++)
        #pragma unroll
        for (int nt = 0; nt < 8; nt++)
            acc[mt][nt] = make_float4(0.f, 0.f, 0.f, 0.f);

    #pragma unroll
    for (int kt = 0; kt < 16; kt++) {
        int k0 = kt * 8 + kq;
        uint32_t a[2][4];
        #pragma unroll
        for (int mt = 0; mt < 2; mt++) {
            int r0 = (rg * 32 + mt * 16 + row_l) * PAD;
            a[mt][0] = __float_as_uint(As[r0 + k0]);
            a[mt][1] = __float_as_uint(As[r0 + 8 * PAD + k0]);
            a[mt][2] = __float_as_uint(As[r0 + k0 + 4]);
            a[mt][3] = __float_as_uint(As[r0 + 8 * PAD + k0 + 4]);
        }
        #pragma unroll
        for (int nt = 0; nt < 8; nt++) {
            int ntg = cg * 8 + nt;
            float2 b = *(float2*)&Wf[((ntg * 16 + kt) * 32 + lane) * 2];
            uint32_t b0 = __float_as_uint(b.x);
            uint32_t b1 = __float_as_uint(b.y);
            mma_tf32(acc[0][nt], a[0][0], a[0][1], a[0][2], a[0][3], b0, b1);
            mma_tf32(acc[1][nt], a[1][0], a[1][1], a[1][2], a[1][3], b0, b1);
        }
    }

    // store: c0,c1 -> (row, col..col+1), c2,c3 -> (row+8, ...)
    #pragma unroll
    for (int mt = 0; mt < 2; mt++) {
        int grow = rb + rg * 32 + mt * 16 + row_l;
        #pragma unroll
        for (int nt = 0; nt < 8; nt++) {
            int col = cg * 64 + nt * 8 + 2 * kq;
            if (grow < NN)
                *(float2*)&g_xw[(size_t)grow * HD + col] =
                    make_float2(acc[mt][nt].x, acc[mt][nt].y);
            if (grow + 8 < NN)
                *(float2*)&g_xw[(size_t)(grow + 8) * HD + col] =
                    make_float2(acc[mt][nt].z, acc[mt][nt].w);
        }
    }
}

// ---------------- conv aggregation (gather, no atomics, exact fp32) ----------
__global__ void k_gather(const float* __restrict__ bias,
                         float* __restrict__ out, int do_relu) {
    int gtid = blockIdx.x * blockDim.x + threadIdx.x;
    int node = gtid >> 5;
    int lane = gtid & 31;
    if (node >= NN) return;

    const float4* xw4 = (const float4*)g_xw;
    float s  = g_dinv[node];
    float ss = s * s;
    float4 a = xw4[(size_t)node * 32 + lane];
    float4 acc = make_float4(ss * a.x, ss * a.y, ss * a.z, ss * a.w);

    int e0 = g_rowptr[node], e1 = g_rowptr[node + 1];
    for (int e = e0; e < e1; e++) {
        int j = g_csr[e];
        float c = s * g_dinv[j];
        float4 v = xw4[(size_t)j * 32 + lane];
        acc.x += c * v.x; acc.y += c * v.y; acc.z += c * v.z; acc.w += c * v.w;
    }
    float4 bb = ((const float4*)bias)[lane];
    acc.x += bb.x; acc.y += bb.y; acc.z += bb.z; acc.w += bb.w;
    if (do_relu) {
        acc.x = fmaxf(acc.x, 0.f); acc.y = fmaxf(acc.y, 0.f);
        acc.z = fmaxf(acc.z, 0.f); acc.w = fmaxf(acc.w, 0.f);
    }
    ((float4*)out)[(size_t)node * 32 + lane] = acc;
}

// ---------------- pooling + MLP head (matmuls in tf32) ----------------
__global__ void k_pool(const float* __restrict__ x,
                       const float* __restrict__ l1w,
                       const float* __restrict__ l1b,
                       const float* __restrict__ l2w,
                       const float* __restrict__ l2b,
                       float* __restrict__ out) {
    __shared__ float h[HD];
    __shared__ float red[4];
    int g = blockIdx.x, t = threadIdx.x;
    long long n0 = (long long)g * 200;
    h[t] = tf32r(x[n0 * HD + t] * x[(n0 + 1) * HD + t]);
    __syncthreads();
    float acc = l1b[t];
    #pragma unroll 16
    for (int i = 0; i < HD; i++) acc += h[i] * tf32r(l1w[i * HD + t]);
    acc = fmaxf(acc, 0.f);
    float p = tf32r(acc) * tf32r(l2w[t]);
    #pragma unroll
    for (int o = 16; o; o >>= 1) p += __shfl_xor_sync(0xffffffffu, p, o);
    if ((t & 31) == 0) red[t >> 5] = p;
    __syncthreads();
    if (t == 0) out[g] = red[0] + red[1] + red[2] + red[3] + l2b[0];
}

// ---------------- launch ----------------
extern "C" void kernel_launch(void* const* d_in, const int* in_sizes, int n_in,
                              void* d_out, int out_size) {
    const int*           z    = (const int*)d_in[0];
    const int*           ei   = (const int*)d_in[1];
    const unsigned char* mask = (const unsigned char*)d_in[3];
    const float* zt  = (const float*)d_in[4];
    const float* W0  = (const float*)d_in[5];
    const float* b0  = (const float*)d_in[6];
    const float* W1  = (const float*)d_in[7];
    const float* b1  = (const float*)d_in[8];
    const float* W2  = (const float*)d_in[9];
    const float* b2  = (const float*)d_in[10];
    const float* l1w = (const float*)d_in[11];
    const float* l1b = (const float*)d_in[12];
    const float* l2w = (const float*)d_in[13];
    const float* l2b = (const float*)d_in[14];
    float* out = (float*)d_out;

    const int* src = ei;
    const int* dst = ei + NE;

    float *px = nullptr, *py = nullptr;
    cudaGetSymbolAddress((void**)&px, g_x);
    cudaGetSymbolAddress((void**)&py, g_y);

    const int GEMM_SMEM = (128 * PAD + 16384) * sizeof(float);   // 133,120 B
    static int smem_set = 0;
    if (!smem_set) {
        cudaFuncSetAttribute(k_gemm_tc,
                             cudaFuncAttributeMaxDynamicSharedMemorySize,
                             GEMM_SMEM);
        smem_set = 1;
    }

    // mask dtype sniff (int32 bool vs uint8 bool)
    k_detect<<<1, 256>>>(mask);

    // embedding + W fragment packing
    k_embed<<<(NN * 32 + 255) / 256, 256>>>(z, zt);
    kw_pack<<<3, 256>>>(W0, W1, W2);

    // CSR + dinv (shared by all 3 layers)
    k_zero_cnt<<<(NN + 255) / 256, 256>>>();
    k_count<<<(NE + 255) / 256, 256>>>(dst, mask);
    k_dinv<<<(NN + 255) / 256, 256>>>();
    k_scan1<<<NBLK, SCAN_B>>>();
    k_scan2<<<1, 128>>>();
    k_scan3<<<(NN + 255) / 256, 256>>>();
    k_fill<<<(NE + 255) / 256, 256>>>(src, dst, mask);

    int ggrid = (NN + 127) / 128;   // 782

    // layer 0: x -> y (relu)
    k_gemm_tc<<<ggrid, 256, GEMM_SMEM>>>(px, 0);
    k_gather<<<(NN * 32 + 255) / 256, 256>>>(b0, py, 1);
    // layer 1: y -> x (relu)
    k_gemm_tc<<<ggrid, 256, GEMM_SMEM>>>(py, 1);
    k_gather<<<(NN * 32 + 255) / 256, 256>>>(b1, px, 1);
    // layer 2: x -> y (no relu)
    k_gemm_tc<<<ggrid, 256, GEMM_SMEM>>>(px, 2);
    k_gather<<<(NN * 32 + 255) / 256, 256>>>(b2, py, 0);

    // pool + MLP
    k_pool<<<NG, HD>>>(py, l1w, l1b, l2w, l2b, out);
}

// round 6
// speedup vs baseline: 1.7900x; 1.3972x over previous
#include <cuda_runtime.h>
#include <cstdint>

#define NN 100000
#define NE 800000
#define HD 128
#define NG 500
#define SCAN_B 1024
#define NBLK ((NN + SCAN_B - 1) / SCAN_B)   // 98
#define PAD 132                              // A-tile row stride (floats)
#define GROWS 256                            // GEMM rows per block

// ---------------- scratch (device globals; no allocation) ----------------
__device__ float g_x [NN * HD];   // ping
__device__ float g_y [NN * HD];   // pong
__device__ float g_xw[NN * HD];   // x @ W
__device__ float g_wf[3 * 16384]; // pre-packed W B-fragments (3 layers)
__device__ float g_dinv[NN];
__device__ int   g_cnt[NN];
__device__ int   g_rowptr[NN + 1];
__device__ int   g_cursor[NN];
__device__ int   g_csr[NE];       // src node per (dst-sorted) live edge
__device__ int   g_bsum[128];
__device__ int   g_mask_i32;      // 1 if edge_mask serialized as int32

// TF32 round (matches GPU tf32 matmul operand rounding)
__device__ __forceinline__ float tf32r(float x) {
    float r;
    asm("cvt.rna.tf32.f32 %0, %1;" : "=f"(r) : "f"(x));
    return r;
}
__device__ __forceinline__ float4 tf32r4(float4 v) {
    return make_float4(tf32r(v.x), tf32r(v.y), tf32r(v.z), tf32r(v.w));
}

__device__ __forceinline__ void mma_tf32(float4& c,
    uint32_t a0, uint32_t a1, uint32_t a2, uint32_t a3,
    uint32_t b0, uint32_t b1) {
    asm volatile(
        "mma.sync.aligned.m16n8k8.row.col.f32.tf32.tf32.f32 "
        "{%0,%1,%2,%3}, {%4,%5,%6,%7}, {%8,%9}, {%0,%1,%2,%3};"
        : "+f"(c.x), "+f"(c.y), "+f"(c.z), "+f"(c.w)
        : "r"(a0), "r"(a1), "r"(a2), "r"(a3), "r"(b0), "r"(b1));
}

// ---------------- mask dtype detection ----------------
__global__ void k_detect(const unsigned char* __restrict__ m) {
    __shared__ int any;
    if (threadIdx.x == 0) any = 0;
    __syncthreads();
    int local = 0;
    for (int i = threadIdx.x; i < 65536; i += blockDim.x)
        if ((i & 3) && m[i]) local = 1;
    if (local) any = 1;                  // benign race
    __syncthreads();
    if (threadIdx.x == 0) g_mask_i32 = (any == 0);
}

__device__ __forceinline__ bool mlive(const unsigned char* m, int e, int is32) {
    if (is32) return ((const int*)m)[e] != 0;
    return m[e] != 0;
}

// ---------------- CSR build ----------------
__global__ void k_zero_cnt() {
    int i = blockIdx.x * blockDim.x + threadIdx.x;
    if (i < NN) g_cnt[i] = 0;
}

__global__ void k_count(const int* __restrict__ dst,
                        const unsigned char* __restrict__ mask) {
    int e = blockIdx.x * blockDim.x + threadIdx.x;
    if (e >= NE) return;
    if (mlive(mask, e, g_mask_i32)) atomicAdd(&g_cnt[dst[e]], 1);
}

// scan1 also emits dinv = rsqrt(cnt+1)
__global__ void k_scan1() {
    __shared__ int s[SCAN_B];
    int i = blockIdx.x * SCAN_B + threadIdx.x;
    int v = (i < NN) ? g_cnt[i] : 0;
    if (i < NN) g_dinv[i] = rsqrtf((float)v + 1.0f);
    s[threadIdx.x] = v;
    __syncthreads();
    for (int off = 1; off < SCAN_B; off <<= 1) {
        int t = (threadIdx.x >= off) ? s[threadIdx.x - off] : 0;
        __syncthreads();
        s[threadIdx.x] += t;
        __syncthreads();
    }
    if (i < NN) g_rowptr[i] = s[threadIdx.x] - v;   // block-local exclusive
    if (threadIdx.x == SCAN_B - 1) g_bsum[blockIdx.x] = s[SCAN_B - 1];
}

__global__ void k_scan2() {   // single block of 128 threads
    __shared__ int s[128];
    int t = threadIdx.x;
    int v = (t < NBLK) ? g_bsum[t] : 0;
    s[t] = v;
    __syncthreads();
    for (int off = 1; off < 128; off <<= 1) {
        int tt = (t >= off) ? s[t - off] : 0;
        __syncthreads();
        s[t] += tt;
        __syncthreads();
    }
    if (t < NBLK) g_bsum[t] = s[t] - v;             // exclusive block offsets
    if (t == NBLK - 1) g_rowptr[NN] = s[t];         // total live edges
}

__global__ void k_scan3() {
    int i = blockIdx.x * blockDim.x + threadIdx.x;
    if (i >= NN) return;
    int r = g_rowptr[i] + g_bsum[i / SCAN_B];
    g_rowptr[i] = r;
    g_cursor[i] = r;
}

__global__ void k_fill(const int* __restrict__ src,
                       const int* __restrict__ dst,
                       const unsigned char* __restrict__ mask) {
    int e = blockIdx.x * blockDim.x + threadIdx.x;
    if (e >= NE) return;
    if (mlive(mask, e, g_mask_i32)) {
        int pos = atomicAdd(&g_cursor[dst[e]], 1);
        g_csr[pos] = src[e];
    }
}

// ---------------- W fragment packing (once per launch, all 3 layers) ----------
// B frag (k8n8, col-major operand) for m16n8k8: b0 = W[k0+lane%4][n0+lane/4],
// b1 = W[k0+4+lane%4][n0+lane/4]. Stored as float2 at [(nt*16+kt)*32+lane].
__global__ void kw_pack(const float* __restrict__ W0,
                        const float* __restrict__ W1,
                        const float* __restrict__ W2) {
    const float* W = (blockIdx.x == 0) ? W0 : (blockIdx.x == 1) ? W1 : W2;
    float2* out = (float2*)(g_wf + blockIdx.x * 16384);
    for (int idx = threadIdx.x; idx < 8192; idx += blockDim.x) {
        int lane = idx & 31, kt = (idx >> 5) & 15, nt = idx >> 9;
        int k = kt * 8 + (lane & 3);
        int n = nt * 8 + (lane >> 2);
        float b0 = tf32r(W[k * HD + n]);
        float b1 = tf32r(W[(k + 4) * HD + n]);
        out[idx] = make_float2(b0, b1);
    }
}

// ---------------- tensor-core GEMM: g_xw = tf32(A)[N,128] @ tf32(W)[128,128] --
// 512 threads / 16 warps. Warp grid 8 (rows) x 2 (cols). Per warp: 32 rows x 64
// cols = 2 m-tiles x 8 n-tiles of m16n8, K = 128 in 16 k8 steps.
// If z != nullptr, A rows come from zt[z[row]] (fused embedding, layer 0).
__global__ __launch_bounds__(512)
void k_gemm_tc(const float* __restrict__ A,
               const int* __restrict__ z,
               const float* __restrict__ zt,
               int layer) {
    extern __shared__ float sm[];
    float* As = sm;                   // GROWS x PAD floats
    float* Wf = sm + GROWS * PAD;     // 16384 floats

    int rb = blockIdx.x * GROWS;
    int t = threadIdx.x;

    // stage A tile (tf32-rounded, zero-fill past NN)
    for (int i = t; i < GROWS * 32; i += 512) {
        int row = i >> 5, c4 = i & 31;
        int gr = rb + row;
        float4 v = make_float4(0.f, 0.f, 0.f, 0.f);
        if (gr < NN) {
            const float4* srow = z ? (const float4*)zt + (size_t)z[gr] * 32
                                   : (const float4*)A  + (size_t)gr   * 32;
            v = srow[c4];
        }
        *(float4*)&As[row * PAD + c4 * 4] = tf32r4(v);
    }
    // stage packed W
    const float4* wsrc = (const float4*)(g_wf + layer * 16384);
    for (int i = t; i < 4096; i += 512) ((float4*)Wf)[i] = wsrc[i];
    __syncthreads();

    int wid = t >> 5, lane = t & 31;
    int rg = wid & 7;          // row group (32 rows each)
    int cg = wid >> 3;         // col group (64 cols each)
    int row_l = lane >> 2;     // 0..7
    int kq = lane & 3;         // 0..3

    float4 acc[2][8];
    #pragma unroll
    for (int mt = 0; mt < 2; mt++)
        #pragma unroll
        for (int nt = 0; nt < 8; nt++)
            acc[mt][nt] = make_float4(0.f, 0.f, 0.f, 0.f);

    #pragma unroll
    for (int kt = 0; kt < 16; kt++) {
        int k0 = kt * 8 + kq;
        uint32_t a[2][4];
        #pragma unroll
        for (int mt = 0; mt < 2; mt++) {
            int r0 = (rg * 32 + mt * 16 + row_l) * PAD;
            a[mt][0] = __float_as_uint(As[r0 + k0]);
            a[mt][1] = __float_as_uint(As[r0 + 8 * PAD + k0]);
            a[mt][2] = __float_as_uint(As[r0 + k0 + 4]);
            a[mt][3] = __float_as_uint(As[r0 + 8 * PAD + k0 + 4]);
        }
        #pragma unroll
        for (int nt = 0; nt < 8; nt++) {
            int ntg = cg * 8 + nt;
            float2 b = *(float2*)&Wf[((ntg * 16 + kt) * 32 + lane) * 2];
            uint32_t b0 = __float_as_uint(b.x);
            uint32_t b1 = __float_as_uint(b.y);
            mma_tf32(acc[0][nt], a[0][0], a[0][1], a[0][2], a[0][3], b0, b1);
            mma_tf32(acc[1][nt], a[1][0], a[1][1], a[1][2], a[1][3], b0, b1);
        }
    }

    // store: c0,c1 -> (row, col..col+1), c2,c3 -> (row+8, ...)
    #pragma unroll
    for (int mt = 0; mt < 2; mt++) {
        int grow = rb + rg * 32 + mt * 16 + row_l;
        #pragma unroll
        for (int nt = 0; nt < 8; nt++) {
            int col = cg * 64 + nt * 8 + 2 * kq;
            if (grow < NN)
                *(float2*)&g_xw[(size_t)grow * HD + col] =
                    make_float2(acc[mt][nt].x, acc[mt][nt].y);
            if (grow + 8 < NN)
                *(float2*)&g_xw[(size_t)(grow + 8) * HD + col] =
                    make_float2(acc[mt][nt].z, acc[mt][nt].w);
        }
    }
}

// ---------------- conv aggregation (gather, no atomics, exact fp32) ----------
__global__ void k_gather(const float* __restrict__ bias,
                         float* __restrict__ out, int do_relu) {
    int gtid = blockIdx.x * blockDim.x + threadIdx.x;
    int node = gtid >> 5;
    int lane = gtid & 31;
    if (node >= NN) return;

    const float4* xw4 = (const float4*)g_xw;
    float s  = g_dinv[node];
    float ss = s * s;
    float4 a = xw4[(size_t)node * 32 + lane];
    float4 acc = make_float4(ss * a.x, ss * a.y, ss * a.z, ss * a.w);

    int e0 = g_rowptr[node], e1 = g_rowptr[node + 1];
    for (int e = e0; e < e1; e++) {
        int j = g_csr[e];
        float c = s * g_dinv[j];
        float4 v = xw4[(size_t)j * 32 + lane];
        acc.x += c * v.x; acc.y += c * v.y; acc.z += c * v.z; acc.w += c * v.w;
    }
    float4 bb = ((const float4*)bias)[lane];
    acc.x += bb.x; acc.y += bb.y; acc.z += bb.z; acc.w += bb.w;
    if (do_relu) {
        acc.x = fmaxf(acc.x, 0.f); acc.y = fmaxf(acc.y, 0.f);
        acc.z = fmaxf(acc.z, 0.f); acc.w = fmaxf(acc.w, 0.f);
    }
    ((float4*)out)[(size_t)node * 32 + lane] = acc;
}

// ---------------- pooling + MLP head (matmuls in tf32) ----------------
__global__ void k_pool(const float* __restrict__ x,
                       const float* __restrict__ l1w,
                       const float* __restrict__ l1b,
                       const float* __restrict__ l2w,
                       const float* __restrict__ l2b,
                       float* __restrict__ out) {
    __shared__ float h[HD];
    __shared__ float red[4];
    int g = blockIdx.x, t = threadIdx.x;
    long long n0 = (long long)g * 200;
    h[t] = tf32r(x[n0 * HD + t] * x[(n0 + 1) * HD + t]);
    __syncthreads();
    float acc = l1b[t];
    #pragma unroll 16
    for (int i = 0; i < HD; i++) acc += h[i] * tf32r(l1w[i * HD + t]);
    acc = fmaxf(acc, 0.f);
    float p = tf32r(acc) * tf32r(l2w[t]);
    #pragma unroll
    for (int o = 16; o; o >>= 1) p += __shfl_xor_sync(0xffffffffu, p, o);
    if ((t & 31) == 0) red[t >> 5] = p;
    __syncthreads();
    if (t == 0) out[g] = red[0] + red[1] + red[2] + red[3] + l2b[0];
}

// ---------------- launch ----------------
extern "C" void kernel_launch(void* const* d_in, const int* in_sizes, int n_in,
                              void* d_out, int out_size) {
    const int*           z    = (const int*)d_in[0];
    const int*           ei   = (const int*)d_in[1];
    const unsigned char* mask = (const unsigned char*)d_in[3];
    const float* zt  = (const float*)d_in[4];
    const float* W0  = (const float*)d_in[5];
    const float* b0  = (const float*)d_in[6];
    const float* W1  = (const float*)d_in[7];
    const float* b1  = (const float*)d_in[8];
    const float* W2  = (const float*)d_in[9];
    const float* b2  = (const float*)d_in[10];
    const float* l1w = (const float*)d_in[11];
    const float* l1b = (const float*)d_in[12];
    const float* l2w = (const float*)d_in[13];
    const float* l2b = (const float*)d_in[14];
    float* out = (float*)d_out;

    const int* src = ei;
    const int* dst = ei + NE;

    float *px = nullptr, *py = nullptr;
    cudaGetSymbolAddress((void**)&px, g_x);
    cudaGetSymbolAddress((void**)&py, g_y);

    const int GEMM_SMEM = (GROWS * PAD + 16384) * sizeof(float);  // 200,704 B
    cudaFuncSetAttribute(k_gemm_tc,
                         cudaFuncAttributeMaxDynamicSharedMemorySize,
                         GEMM_SMEM);

    int ggrid = (NN + GROWS - 1) / GROWS;   // 391

    // 1: mask dtype sniff
    k_detect<<<1, 256>>>(mask);
    // 2: W fragment packing
    kw_pack<<<3, 256>>>(W0, W1, W2);
    // 3: zero degree counters
    k_zero_cnt<<<(NN + 255) / 256, 256>>>();
    // 4: layer-0 GEMM with fused embedding (position 4 => ncu captures this)
    k_gemm_tc<<<ggrid, 512, GEMM_SMEM>>>(nullptr, z, zt, 0);
    // 5..9: CSR + dinv (shared by all 3 layers)
    k_count<<<(NE + 255) / 256, 256>>>(dst, mask);
    k_scan1<<<NBLK, SCAN_B>>>();
    k_scan2<<<1, 128>>>();
    k_scan3<<<(NN + 255) / 256, 256>>>();
    k_fill<<<(NE + 255) / 256, 256>>>(src, dst, mask);

    // layer 0 aggregate: xw -> y (relu)
    k_gather<<<(NN * 32 + 255) / 256, 256>>>(b0, py, 1);
    // layer 1: y -> x (relu)
    k_gemm_tc<<<ggrid, 512, GEMM_SMEM>>>(py, nullptr, nullptr, 1);
    k_gather<<<(NN * 32 + 255) / 256, 256>>>(b1, px, 1);
    // layer 2: x -> y (no relu)
    k_gemm_tc<<<ggrid, 512, GEMM_SMEM>>>(px, nullptr, nullptr, 2);
    k_gather<<<(NN * 32 + 255) / 256, 256>>>(b2, py, 0);

    // pool + MLP
    k_pool<<<NG, HD>>>(py, l1w, l1b, l2w, l2b, out);
}

// round 7
// speedup vs baseline: 3.3424x; 1.8673x over previous
#include <cuda_runtime.h>
#include <cstdint>

#define NN 100000
#define NE 800000
#define HD 128
#define NG 500
#define SCAN_B 1024
#define NBLK ((NN + SCAN_B - 1) / SCAN_B)   // 98
#define PAD 132                              // A-tile row stride (floats)
#define GROWS 256                            // GEMM rows per block
#define CAP2 8192                            // list2 capacity (S2)
#define CAP1 65536                           // list1 capacity (S1)

// ---------------- scratch (device globals; no allocation) ----------------
__device__ float g_x [NN * HD];   // ping
__device__ float g_y [NN * HD];   // pong
__device__ float g_xw[NN * HD];   // x @ W
__device__ float g_wf[3 * 16384]; // pre-packed W B-fragments (3 layers)
__device__ float g_dinv[NN];
__device__ int   g_cnt[NN];
__device__ int   g_rowptr[NN + 1];
__device__ int   g_cursor[NN];
__device__ int   g_csr[NE];       // src node per (dst-sorted) live edge
__device__ int   g_bsum[128];
__device__ int   g_mask_i32;      // 1 if edge_mask serialized as int32
__device__ int   g_list1[CAP1];   // S1 = S2 + neighbors(S2)
__device__ int   g_list2[CAP2];   // S2 = centers + neighbors(centers)
__device__ int   g_len1;
__device__ int   g_len2;

// TF32 round (matches GPU tf32 matmul operand rounding)
__device__ __forceinline__ float tf32r(float x) {
    float r;
    asm("cvt.rna.tf32.f32 %0, %1;" : "=f"(r) : "f"(x));
    return r;
}
__device__ __forceinline__ float4 tf32r4(float4 v) {
    return make_float4(tf32r(v.x), tf32r(v.y), tf32r(v.z), tf32r(v.w));
}

__device__ __forceinline__ void mma_tf32(float4& c,
    uint32_t a0, uint32_t a1, uint32_t a2, uint32_t a3,
    uint32_t b0, uint32_t b1) {
    asm volatile(
        "mma.sync.aligned.m16n8k8.row.col.f32.tf32.tf32.f32 "
        "{%0,%1,%2,%3}, {%4,%5,%6,%7}, {%8,%9}, {%0,%1,%2,%3};"
        : "+f"(c.x), "+f"(c.y), "+f"(c.z), "+f"(c.w)
        : "r"(a0), "r"(a1), "r"(a2), "r"(a3), "r"(b0), "r"(b1));
}

// ---------------- mask dtype detection (+ counter init) ----------------
__global__ void k_detect(const unsigned char* __restrict__ m) {
    __shared__ int any;
    if (threadIdx.x == 0) any = 0;
    __syncthreads();
    int local = 0;
    for (int i = threadIdx.x; i < 65536; i += blockDim.x)
        if ((i & 3) && m[i]) local = 1;
    if (local) any = 1;                  // benign race
    __syncthreads();
    if (threadIdx.x == 0) {
        g_mask_i32 = (any == 0);
        g_len2 = 1000;                   // append cursor for list2
    }
}

__device__ __forceinline__ bool mlive(const unsigned char* m, int e, int is32) {
    if (is32) return ((const int*)m)[e] != 0;
    return m[e] != 0;
}

// ---------------- CSR build ----------------
__global__ void k_zero_cnt() {
    int i = blockIdx.x * blockDim.x + threadIdx.x;
    if (i < NN) g_cnt[i] = 0;
}

__global__ void k_count(const int* __restrict__ dst,
                        const unsigned char* __restrict__ mask) {
    int e = blockIdx.x * blockDim.x + threadIdx.x;
    if (e >= NE) return;
    if (mlive(mask, e, g_mask_i32)) atomicAdd(&g_cnt[dst[e]], 1);
}

// scan1 also emits dinv = rsqrt(cnt+1)
__global__ void k_scan1() {
    __shared__ int s[SCAN_B];
    int i = blockIdx.x * SCAN_B + threadIdx.x;
    int v = (i < NN) ? g_cnt[i] : 0;
    if (i < NN) g_dinv[i] = rsqrtf((float)v + 1.0f);
    s[threadIdx.x] = v;
    __syncthreads();
    for (int off = 1; off < SCAN_B; off <<= 1) {
        int t = (threadIdx.x >= off) ? s[threadIdx.x - off] : 0;
        __syncthreads();
        s[threadIdx.x] += t;
        __syncthreads();
    }
    if (i < NN) g_rowptr[i] = s[threadIdx.x] - v;   // block-local exclusive
    if (threadIdx.x == SCAN_B - 1) g_bsum[blockIdx.x] = s[SCAN_B - 1];
}

__global__ void k_scan2() {   // single block of 128 threads
    __shared__ int s[128];
    int t = threadIdx.x;
    int v = (t < NBLK) ? g_bsum[t] : 0;
    s[t] = v;
    __syncthreads();
    for (int off = 1; off < 128; off <<= 1) {
        int tt = (t >= off) ? s[t - off] : 0;
        __syncthreads();
        s[t] += tt;
        __syncthreads();
    }
    if (t < NBLK) g_bsum[t] = s[t] - v;             // exclusive block offsets
    if (t == NBLK - 1) g_rowptr[NN] = s[t];         // total live edges
}

__global__ void k_scan3() {
    int i = blockIdx.x * blockDim.x + threadIdx.x;
    if (i >= NN) return;
    int r = g_rowptr[i] + g_bsum[i / SCAN_B];
    g_rowptr[i] = r;
    g_cursor[i] = r;
}

__global__ void k_fill(const int* __restrict__ src,
                       const int* __restrict__ dst,
                       const unsigned char* __restrict__ mask) {
    int e = blockIdx.x * blockDim.x + threadIdx.x;
    if (e >= NE) return;
    if (mlive(mask, e, g_mask_i32)) {
        int pos = atomicAdd(&g_cursor[dst[e]], 1);
        g_csr[pos] = src[e];
    }
}

// ---------------- dependency-set expansion ----------------
// list2 = centers + in-neighbors(centers)
__global__ void k_expand0() {
    int i = blockIdx.x * blockDim.x + threadIdx.x;
    if (i >= 1000) return;
    int n = (i >> 1) * 200 + (i & 1);
    g_list2[i] = n;
    int e0 = g_rowptr[n], e1 = g_rowptr[n + 1];
    for (int e = e0; e < e1; e++) {
        int pos = atomicAdd(&g_len2, 1);
        if (pos < CAP2) g_list2[pos] = g_csr[e];
    }
}

__global__ void k_len1() { g_len1 = min(g_len2, CAP2); }

// list1 = list2 + in-neighbors(list2)
__global__ void k_expand1() {
    int i = blockIdx.x * blockDim.x + threadIdx.x;
    int len2 = min(g_len2, CAP2);
    if (i >= len2) return;
    int n = g_list2[i];
    g_list1[i] = n;
    int e0 = g_rowptr[n], e1 = g_rowptr[n + 1];
    for (int e = e0; e < e1; e++) {
        int pos = atomicAdd(&g_len1, 1);
        if (pos < CAP1) g_list1[pos] = g_csr[e];
    }
}

// ---------------- W fragment packing (once per launch, all 3 layers) ----------
__global__ void kw_pack(const float* __restrict__ W0,
                        const float* __restrict__ W1,
                        const float* __restrict__ W2) {
    const float* W = (blockIdx.x == 0) ? W0 : (blockIdx.x == 1) ? W1 : W2;
    float2* out = (float2*)(g_wf + blockIdx.x * 16384);
    for (int idx = threadIdx.x; idx < 8192; idx += blockDim.x) {
        int lane = idx & 31, kt = (idx >> 5) & 15, nt = idx >> 9;
        int k = kt * 8 + (lane & 3);
        int n = nt * 8 + (lane >> 2);
        float b0 = tf32r(W[k * HD + n]);
        float b1 = tf32r(W[(k + 4) * HD + n]);
        out[idx] = make_float2(b0, b1);
    }
}

// ---------------- tensor-core GEMM with optional row-list -------------------
// 512 threads / 16 warps, 8 rg x 2 cg, warp tile 32x64, K=128 in 16 k8 steps.
// Double-buffered fragment registers for latency hiding.
__global__ __launch_bounds__(512)
void k_gemm_tc(const float* __restrict__ A,
               const int* __restrict__ z,
               const float* __restrict__ zt,
               int layer,
               const int* __restrict__ list,
               const int* __restrict__ lenp,
               int cap) {
    extern __shared__ float sm[];
    float* As = sm;                       // GROWS x PAD floats
    float* Wf = sm + GROWS * PAD;         // 16384 floats
    int*   Rid = (int*)(Wf + 16384);      // GROWS row ids

    int rb = blockIdx.x * GROWS;
    int len = NN;
    if (list) {
        len = min(*lenp, cap);
        if (rb >= len) return;
    }
    int t = threadIdx.x;
    if (t < GROWS) {
        int li = rb + t;
        int r = -1;
        if (li < len) r = list ? list[li] : li;
        Rid[t] = r;
    }
    __syncthreads();

    // stage A tile (tf32-rounded; zero-fill invalid rows)
    for (int i = t; i < GROWS * 32; i += 512) {
        int row = i >> 5, c4 = i & 31;
        int r = Rid[row];
        float4 v = make_float4(0.f, 0.f, 0.f, 0.f);
        if (r >= 0) {
            const float4* srow = z ? (const float4*)zt + (size_t)z[r] * 32
                                   : (const float4*)A  + (size_t)r    * 32;
            v = srow[c4];
        }
        *(float4*)&As[row * PAD + c4 * 4] = tf32r4(v);
    }
    // stage packed W
    const float4* wsrc = (const float4*)(g_wf + layer * 16384);
    for (int i = t; i < 4096; i += 512) ((float4*)Wf)[i] = wsrc[i];
    __syncthreads();

    int wid = t >> 5, lane = t & 31;
    int rg = wid & 7;          // row group (32 rows each)
    int cg = wid >> 3;         // col group (64 cols each)
    int row_l = lane >> 2;     // 0..7
    int kq = lane & 3;         // 0..3

    float4 acc[2][8];
    #pragma unroll
    for (int mt = 0; mt < 2; mt++)
        #pragma unroll
        for (int nt = 0; nt < 8; nt++)
            acc[mt][nt] = make_float4(0.f, 0.f, 0.f, 0.f);

    uint32_t a[2][4];
    float2   b[8];
    // prologue loads for kt=0
    #pragma unroll
    for (int mt = 0; mt < 2; mt++) {
        int base = (rg * 32 + mt * 16 + row_l) * PAD + kq;
        a[mt][0] = __float_as_uint(As[base]);
        a[mt][1] = __float_as_uint(As[base + 8 * PAD]);
        a[mt][2] = __float_as_uint(As[base + 4]);
        a[mt][3] = __float_as_uint(As[base + 8 * PAD + 4]);
    }
    #pragma unroll
    for (int nt = 0; nt < 8; nt++)
        b[nt] = *(float2*)&Wf[(((cg * 8 + nt) * 16 + 0) * 32 + lane) * 2];

    #pragma unroll
    for (int kt = 0; kt < 16; kt++) {
        uint32_t an[2][4];
        float2   bn[8];
        if (kt < 15) {
            int k0 = (kt + 1) * 8 + kq;
            #pragma unroll
            for (int mt = 0; mt < 2; mt++) {
                int base = (rg * 32 + mt * 16 + row_l) * PAD + k0;
                an[mt][0] = __float_as_uint(As[base]);
                an[mt][1] = __float_as_uint(As[base + 8 * PAD]);
                an[mt][2] = __float_as_uint(As[base + 4]);
                an[mt][3] = __float_as_uint(As[base + 8 * PAD + 4]);
            }
            #pragma unroll
            for (int nt = 0; nt < 8; nt++)
                bn[nt] = *(float2*)&Wf[(((cg * 8 + nt) * 16 + kt + 1) * 32 + lane) * 2];
        }
        #pragma unroll
        for (int nt = 0; nt < 8; nt++) {
            uint32_t b0 = __float_as_uint(b[nt].x);
            uint32_t b1 = __float_as_uint(b[nt].y);
            mma_tf32(acc[0][nt], a[0][0], a[0][1], a[0][2], a[0][3], b0, b1);
            mma_tf32(acc[1][nt], a[1][0], a[1][1], a[1][2], a[1][3], b0, b1);
        }
        if (kt < 15) {
            #pragma unroll
            for (int mt = 0; mt < 2; mt++)
                #pragma unroll
                for (int q = 0; q < 4; q++) a[mt][q] = an[mt][q];
            #pragma unroll
            for (int nt = 0; nt < 8; nt++) b[nt] = bn[nt];
        }
    }

    // scatter store via row ids
    #pragma unroll
    for (int mt = 0; mt < 2; mt++) {
        int lrow = rg * 32 + mt * 16 + row_l;
        int r0 = Rid[lrow];
        int r8 = Rid[lrow + 8];
        #pragma unroll
        for (int nt = 0; nt < 8; nt++) {
            int col = cg * 64 + nt * 8 + 2 * kq;
            if (r0 >= 0)
                *(float2*)&g_xw[(size_t)r0 * HD + col] =
                    make_float2(acc[mt][nt].x, acc[mt][nt].y);
            if (r8 >= 0)
                *(float2*)&g_xw[(size_t)r8 * HD + col] =
                    make_float2(acc[mt][nt].z, acc[mt][nt].w);
        }
    }
}

// ---------------- conv aggregation (gather, no atomics, exact fp32) ----------
// modes: centers=1 -> 1000 pooled nodes; list!=null -> list rows; else all NN
__global__ void k_gather(const float* __restrict__ bias,
                         float* __restrict__ out, int do_relu,
                         const int* __restrict__ list,
                         const int* __restrict__ lenp, int cap, int centers) {
    int warp_g = (blockIdx.x * blockDim.x + threadIdx.x) >> 5;
    int lane = threadIdx.x & 31;
    int node;
    if (centers) {
        if (warp_g >= 1000) return;
        node = (warp_g >> 1) * 200 + (warp_g & 1);
    } else if (list) {
        int len = min(*lenp, cap);
        if (warp_g >= len) return;
        node = list[warp_g];
    } else {
        if (warp_g >= NN) return;
        node = warp_g;
    }

    const float4* xw4 = (const float4*)g_xw;
    float s  = g_dinv[node];
    float ss = s * s;
    float4 aa = xw4[(size_t)node * 32 + lane];
    float4 acc = make_float4(ss * aa.x, ss * aa.y, ss * aa.z, ss * aa.w);

    int e0 = g_rowptr[node], e1 = g_rowptr[node + 1];
    for (int e = e0; e < e1; e++) {
        int j = g_csr[e];
        float c = s * g_dinv[j];
        float4 v = xw4[(size_t)j * 32 + lane];
        acc.x += c * v.x; acc.y += c * v.y; acc.z += c * v.z; acc.w += c * v.w;
    }
    float4 bb = ((const float4*)bias)[lane];
    acc.x += bb.x; acc.y += bb.y; acc.z += bb.z; acc.w += bb.w;
    if (do_relu) {
        acc.x = fmaxf(acc.x, 0.f); acc.y = fmaxf(acc.y, 0.f);
        acc.z = fmaxf(acc.z, 0.f); acc.w = fmaxf(acc.w, 0.f);
    }
    ((float4*)out)[(size_t)node * 32 + lane] = acc;
}

// ---------------- pooling + MLP head (matmuls in tf32) ----------------
__global__ void k_pool(const float* __restrict__ x,
                       const float* __restrict__ l1w,
                       const float* __restrict__ l1b,
                       const float* __restrict__ l2w,
                       const float* __restrict__ l2b,
                       float* __restrict__ out) {
    __shared__ float h[HD];
    __shared__ float red[4];
    int g = blockIdx.x, t = threadIdx.x;
    long long n0 = (long long)g * 200;
    h[t] = tf32r(x[n0 * HD + t] * x[(n0 + 1) * HD + t]);
    __syncthreads();
    float acc = l1b[t];
    #pragma unroll 16
    for (int i = 0; i < HD; i++) acc += h[i] * tf32r(l1w[i * HD + t]);
    acc = fmaxf(acc, 0.f);
    float p = tf32r(acc) * tf32r(l2w[t]);
    #pragma unroll
    for (int o = 16; o; o >>= 1) p += __shfl_xor_sync(0xffffffffu, p, o);
    if ((t & 31) == 0) red[t >> 5] = p;
    __syncthreads();
    if (t == 0) out[g] = red[0] + red[1] + red[2] + red[3] + l2b[0];
}

// ---------------- launch ----------------
extern "C" void kernel_launch(void* const* d_in, const int* in_sizes, int n_in,
                              void* d_out, int out_size) {
    const int*           z    = (const int*)d_in[0];
    const int*           ei   = (const int*)d_in[1];
    const unsigned char* mask = (const unsigned char*)d_in[3];
    const float* zt  = (const float*)d_in[4];
    const float* W0  = (const float*)d_in[5];
    const float* b0  = (const float*)d_in[6];
    const float* W1  = (const float*)d_in[7];
    const float* b1  = (const float*)d_in[8];
    const float* W2  = (const float*)d_in[9];
    const float* b2  = (const float*)d_in[10];
    const float* l1w = (const float*)d_in[11];
    const float* l1b = (const float*)d_in[12];
    const float* l2w = (const float*)d_in[13];
    const float* l2b = (const float*)d_in[14];
    float* out = (float*)d_out;

    const int* src = ei;
    const int* dst = ei + NE;

    float *px = nullptr, *py = nullptr;
    int *pl1 = nullptr, *pl2 = nullptr, *plen1 = nullptr, *plen2 = nullptr;
    cudaGetSymbolAddress((void**)&px, g_x);
    cudaGetSymbolAddress((void**)&py, g_y);
    cudaGetSymbolAddress((void**)&pl1, g_list1);
    cudaGetSymbolAddress((void**)&pl2, g_list2);
    cudaGetSymbolAddress((void**)&plen1, g_len1);
    cudaGetSymbolAddress((void**)&plen2, g_len2);

    const int GEMM_SMEM = (GROWS * PAD + 16384) * sizeof(float)
                          + GROWS * sizeof(int);              // 201,728 B
    cudaFuncSetAttribute(k_gemm_tc,
                         cudaFuncAttributeMaxDynamicSharedMemorySize,
                         GEMM_SMEM);

    // 1: mask dtype sniff + counter init
    k_detect<<<1, 256>>>(mask);
    // 2: W fragment packing
    kw_pack<<<3, 256>>>(W0, W1, W2);
    // 3: zero degree counters
    k_zero_cnt<<<(NN + 255) / 256, 256>>>();
    // 4: layer-0 GEMM (full, fused embedding) — ncu slot
    k_gemm_tc<<<(NN + GROWS - 1) / GROWS, 512, GEMM_SMEM>>>(
        nullptr, z, zt, 0, nullptr, nullptr, 0);
    // CSR + dinv
    k_count<<<(NE + 255) / 256, 256>>>(dst, mask);
    k_scan1<<<NBLK, SCAN_B>>>();
    k_scan2<<<1, 128>>>();
    k_scan3<<<(NN + 255) / 256, 256>>>();
    k_fill<<<(NE + 255) / 256, 256>>>(src, dst, mask);
    // dependency lists
    k_expand0<<<4, 256>>>();
    k_len1<<<1, 1>>>();
    k_expand1<<<CAP2 / 256, 256>>>();

    // layer 0 aggregate: xw -> y (relu), only rows in S1
    k_gather<<<CAP1 / 16, 512>>>(b0, py, 1, pl1, plen1, CAP1, 0);
    // layer 1: GEMM on S1 rows, aggregate on S2 rows
    k_gemm_tc<<<CAP1 / GROWS, 512, GEMM_SMEM>>>(py, nullptr, nullptr, 1,
                                                pl1, plen1, CAP1);
    k_gather<<<CAP2 / 16, 512>>>(b1, px, 1, pl2, plen2, CAP2, 0);
    // layer 2: GEMM on S2 rows, aggregate on centers only
    k_gemm_tc<<<CAP2 / GROWS, 512, GEMM_SMEM>>>(px, nullptr, nullptr, 2,
                                                pl2, plen2, CAP2);
    k_gather<<<(1000 * 32 + 511) / 512, 512>>>(b2, py, 0,
                                               nullptr, nullptr, 0, 1);

    // pool + MLP
    k_pool<<<NG, HD>>>(py, l1w, l1b, l2w, l2b, out);
}

// round 8
// speedup vs baseline: 4.3472x; 1.3006x over previous
#include <cuda_runtime.h>
#include <cstdint>

#define NN 100000
#define NE 800000
#define HD 128
#define NG 500
#define SCAN_B 1024
#define NBLK ((NN + SCAN_B - 1) / SCAN_B)   // 98
#define PAD 132                              // A-tile row stride (floats)
#define GROWS 128                            // GEMM rows per block
#define CAP2 8192                            // list2 capacity (S2, unique)
#define CAP1 65536                           // list1 capacity (S1, unique)

// ---------------- scratch (device globals; no allocation) ----------------
__device__ float g_y [NN * HD];   // layer outputs (S1 rows / dense head)
__device__ float g_x2[NN * HD];   // layer-1 output (S2 rows)
__device__ float g_xw[NN * HD];   // aggregated features (GEMM input)
__device__ float g_wf[3 * 16384]; // pre-packed W B-fragments (3 layers)
__device__ float g_dinv[NN];
__device__ int   g_cnt[NN];
__device__ int   g_rowptr[NN + 1];
__device__ int   g_cursor[NN];
__device__ int   g_csr[NE];       // src node per (dst-sorted) live edge
__device__ int   g_bsum[128];
__device__ int   g_mask_i32;      // 1 if edge_mask serialized as int32
__device__ unsigned g_flag[(NN + 31) / 32];  // membership bitmap (dedupe)
__device__ int   g_list1[CAP1];   // S1 = S2 + in-neighbors(S2), unique
__device__ int   g_list2[CAP2];   // S2 = centers + in-neighbors(centers), unique
__device__ int   g_len1;
__device__ int   g_len2;

// TF32 round (matches GPU tf32 matmul operand rounding)
__device__ __forceinline__ float tf32r(float x) {
    float r;
    asm("cvt.rna.tf32.f32 %0, %1;" : "=f"(r) : "f"(x));
    return r;
}
__device__ __forceinline__ float4 tf32r4(float4 v) {
    return make_float4(tf32r(v.x), tf32r(v.y), tf32r(v.z), tf32r(v.w));
}

__device__ __forceinline__ void mma_tf32(float4& c,
    uint32_t a0, uint32_t a1, uint32_t a2, uint32_t a3,
    uint32_t b0, uint32_t b1) {
    asm volatile(
        "mma.sync.aligned.m16n8k8.row.col.f32.tf32.tf32.f32 "
        "{%0,%1,%2,%3}, {%4,%5,%6,%7}, {%8,%9}, {%0,%1,%2,%3};"
        : "+f"(c.x), "+f"(c.y), "+f"(c.z), "+f"(c.w)
        : "r"(a0), "r"(a1), "r"(a2), "r"(a3), "r"(b0), "r"(b1));
}

// ---------------- init: zero counters + flags ----------------
__global__ void k_zero() {
    int i = blockIdx.x * blockDim.x + threadIdx.x;
    if (i < NN) g_cnt[i] = 0;
    if (i < (NN + 31) / 32) g_flag[i] = 0u;
}

// ---------------- mask dtype detection (+ cursor init) ----------------
__global__ void k_detect(const unsigned char* __restrict__ m) {
    __shared__ int any;
    if (threadIdx.x == 0) any = 0;
    __syncthreads();
    int local = 0;
    for (int i = threadIdx.x; i < 65536; i += blockDim.x)
        if ((i & 3) && m[i]) local = 1;
    if (local) any = 1;                  // benign race
    __syncthreads();
    if (threadIdx.x == 0) {
        g_mask_i32 = (any == 0);
        g_len2 = 1000;                   // append cursor (centers occupy 0..999)
    }
}

__device__ __forceinline__ bool mlive(const unsigned char* m, int e, int is32) {
    if (is32) return ((const int*)m)[e] != 0;
    return m[e] != 0;
}

// ---------------- CSR build ----------------
__global__ void k_count(const int* __restrict__ dst,
                        const unsigned char* __restrict__ mask) {
    int e = blockIdx.x * blockDim.x + threadIdx.x;
    if (e >= NE) return;
    if (mlive(mask, e, g_mask_i32)) atomicAdd(&g_cnt[dst[e]], 1);
}

// scan1 also emits dinv = rsqrt(cnt+1)
__global__ void k_scan1() {
    __shared__ int s[SCAN_B];
    int i = blockIdx.x * SCAN_B + threadIdx.x;
    int v = (i < NN) ? g_cnt[i] : 0;
    if (i < NN) g_dinv[i] = rsqrtf((float)v + 1.0f);
    s[threadIdx.x] = v;
    __syncthreads();
    for (int off = 1; off < SCAN_B; off <<= 1) {
        int t = (threadIdx.x >= off) ? s[threadIdx.x - off] : 0;
        __syncthreads();
        s[threadIdx.x] += t;
        __syncthreads();
    }
    if (i < NN) g_rowptr[i] = s[threadIdx.x] - v;
    if (threadIdx.x == SCAN_B - 1) g_bsum[blockIdx.x] = s[SCAN_B - 1];
}

__global__ void k_scan2() {
    __shared__ int s[128];
    int t = threadIdx.x;
    int v = (t < NBLK) ? g_bsum[t] : 0;
    s[t] = v;
    __syncthreads();
    for (int off = 1; off < 128; off <<= 1) {
        int tt = (t >= off) ? s[t - off] : 0;
        __syncthreads();
        s[t] += tt;
        __syncthreads();
    }
    if (t < NBLK) g_bsum[t] = s[t] - v;
    if (t == NBLK - 1) g_rowptr[NN] = s[t];
}

// scan3 also plants centers into list2 and sets their flags
__global__ void k_scan3() {
    int i = blockIdx.x * blockDim.x + threadIdx.x;
    if (i >= NN) return;
    int r = g_rowptr[i] + g_bsum[i / SCAN_B];
    g_rowptr[i] = r;
    g_cursor[i] = r;
    int m = i % 200;
    if (m < 2) {
        int ci = (i / 200) * 2 + m;
        g_list2[ci] = i;
        atomicOr(&g_flag[i >> 5], 1u << (i & 31));
    }
}

__global__ void k_fill(const int* __restrict__ src,
                       const int* __restrict__ dst,
                       const unsigned char* __restrict__ mask) {
    int e = blockIdx.x * blockDim.x + threadIdx.x;
    if (e >= NE) return;
    if (mlive(mask, e, g_mask_i32)) {
        int pos = atomicAdd(&g_cursor[dst[e]], 1);
        g_csr[pos] = src[e];
    }
}

// ---------------- dependency-set expansion (deduped) ----------------
__global__ void k_expand0() {   // neighbors of centers -> list2
    int i = blockIdx.x * blockDim.x + threadIdx.x;
    if (i >= 1000) return;
    int n = (i >> 1) * 200 + (i & 1);
    int e0 = g_rowptr[n], e1 = g_rowptr[n + 1];
    for (int e = e0; e < e1; e++) {
        int j = g_csr[e];
        unsigned bit = 1u << (j & 31);
        unsigned old = atomicOr(&g_flag[j >> 5], bit);
        if (!(old & bit)) {
            int pos = atomicAdd(&g_len2, 1);
            if (pos < CAP2) g_list2[pos] = j;
        }
    }
}

__global__ void k_len1() { g_len1 = min(g_len2, CAP2); }

__global__ void k_expand1() {   // list1 = list2 + neighbors(list2)
    int i = blockIdx.x * blockDim.x + threadIdx.x;
    int len2 = min(g_len2, CAP2);
    if (i >= len2) return;
    int n = g_list2[i];
    g_list1[i] = n;
    int e0 = g_rowptr[n], e1 = g_rowptr[n + 1];
    for (int e = e0; e < e1; e++) {
        int j = g_csr[e];
        unsigned bit = 1u << (j & 31);
        unsigned old = atomicOr(&g_flag[j >> 5], bit);
        if (!(old & bit)) {
            int pos = atomicAdd(&g_len1, 1);
            if (pos < CAP1) g_list1[pos] = j;
        }
    }
}

// ---------------- W fragment packing ----------------
__global__ void kw_pack(const float* __restrict__ W0,
                        const float* __restrict__ W1,
                        const float* __restrict__ W2) {
    const float* W = (blockIdx.x == 0) ? W0 : (blockIdx.x == 1) ? W1 : W2;
    float2* out = (float2*)(g_wf + blockIdx.x * 16384);
    for (int idx = threadIdx.x; idx < 8192; idx += blockDim.x) {
        int lane = idx & 31, kt = (idx >> 5) & 15, nt = idx >> 9;
        int k = kt * 8 + (lane & 3);
        int n = nt * 8 + (lane >> 2);
        out[idx] = make_float2(tf32r(W[k * HD + n]), tf32r(W[(k + 4) * HD + n]));
    }
}

// ---------------- pre-GEMM aggregation (gather, fp32, tf32-rounded feats) ----
// one warp per output row; lane owns float4 of the 128 features.
// layer 0: feature(j) = zt[z[j]] (fused embedding); else feat[j].
// centers_dense: 1000 rows, node = center id, output row = dense index.
__global__ void k_agg(const float* __restrict__ feat,
                      const int* __restrict__ z,
                      const float* __restrict__ zt,
                      float* __restrict__ out,
                      const int* __restrict__ list,
                      const int* __restrict__ lenp, int cap,
                      int centers_dense) {
    int warp_g = (blockIdx.x * blockDim.x + threadIdx.x) >> 5;
    int lane = threadIdx.x & 31;
    int node, orow;
    if (centers_dense) {
        if (warp_g >= 1000) return;
        node = (warp_g >> 1) * 200 + (warp_g & 1);
        orow = warp_g;
    } else {
        int len = min(*lenp, cap);
        if (warp_g >= len) return;
        node = list[warp_g];
        orow = node;
    }

    float s  = g_dinv[node];
    float ss = s * s;

    const float4* zt4 = (const float4*)zt;
    const float4* f4  = (const float4*)feat;

    float4 a = z ? tf32r4(zt4[(size_t)z[node] * 32 + lane])
                 : tf32r4(f4[(size_t)node * 32 + lane]);
    float4 acc = make_float4(ss * a.x, ss * a.y, ss * a.z, ss * a.w);

    int e0 = g_rowptr[node], e1 = g_rowptr[node + 1];
    for (int e = e0; e < e1; e++) {
        int j = g_csr[e];
        float c = s * g_dinv[j];
        float4 v = z ? tf32r4(zt4[(size_t)z[j] * 32 + lane])
                     : tf32r4(f4[(size_t)j * 32 + lane]);
        acc.x += c * v.x; acc.y += c * v.y; acc.z += c * v.z; acc.w += c * v.w;
    }
    ((float4*)out)[(size_t)orow * 32 + lane] = acc;
}

// ---------------- tensor-core GEMM + bias/relu epilogue ----------------
// 256 threads / 8 warps, 4 rg x 2 cg, warp tile 32x64, K=128 in 16 k8 steps.
__global__ __launch_bounds__(256)
void k_gemm_tc(const float* __restrict__ A,
               float* __restrict__ O,
               const float* __restrict__ bias,
               int do_relu, int layer,
               const int* __restrict__ list,
               const int* __restrict__ lenp,
               int cap, int dense_len) {
    extern __shared__ float sm[];
    float* As = sm;                       // GROWS x PAD floats
    float* Wf = sm + GROWS * PAD;         // 16384 floats
    int*   Rid = (int*)(Wf + 16384);      // GROWS row ids

    int rb = blockIdx.x * GROWS;
    int len = dense_len;
    if (list) len = min(*lenp, cap);
    if (rb >= len) return;

    int t = threadIdx.x;
    if (t < GROWS) {
        int li = rb + t;
        Rid[t] = (li < len) ? (list ? list[li] : li) : -1;
    }
    __syncthreads();

    for (int i = t; i < GROWS * 32; i += 256) {
        int row = i >> 5, c4 = i & 31;
        int r = Rid[row];
        float4 v = make_float4(0.f, 0.f, 0.f, 0.f);
        if (r >= 0) v = ((const float4*)A)[(size_t)r * 32 + c4];
        *(float4*)&As[row * PAD + c4 * 4] = tf32r4(v);
    }
    const float4* wsrc = (const float4*)(g_wf + layer * 16384);
    for (int i = t; i < 4096; i += 256) ((float4*)Wf)[i] = wsrc[i];
    __syncthreads();

    int wid = t >> 5, lane = t & 31;
    int rg = wid & 3;          // 4 row groups x 32 rows
    int cg = wid >> 2;         // 2 col groups x 64 cols
    int row_l = lane >> 2;
    int kq = lane & 3;

    float4 acc[2][8];
    #pragma unroll
    for (int mt = 0; mt < 2; mt++)
        #pragma unroll
        for (int nt = 0; nt < 8; nt++)
            acc[mt][nt] = make_float4(0.f, 0.f, 0.f, 0.f);

    uint32_t a[2][4];
    float2   b[8];
    #pragma unroll
    for (int mt = 0; mt < 2; mt++) {
        int base = (rg * 32 + mt * 16 + row_l) * PAD + kq;
        a[mt][0] = __float_as_uint(As[base]);
        a[mt][1] = __float_as_uint(As[base + 8 * PAD]);
        a[mt][2] = __float_as_uint(As[base + 4]);
        a[mt][3] = __float_as_uint(As[base + 8 * PAD + 4]);
    }
    #pragma unroll
    for (int nt = 0; nt < 8; nt++)
        b[nt] = *(float2*)&Wf[(((cg * 8 + nt) * 16) * 32 + lane) * 2];

    #pragma unroll
    for (int kt = 0; kt < 16; kt++) {
        uint32_t an[2][4];
        float2   bn[8];
        if (kt < 15) {
            int k0 = (kt + 1) * 8 + kq;
            #pragma unroll
            for (int mt = 0; mt < 2; mt++) {
                int base = (rg * 32 + mt * 16 + row_l) * PAD + k0;
                an[mt][0] = __float_as_uint(As[base]);
                an[mt][1] = __float_as_uint(As[base + 8 * PAD]);
                an[mt][2] = __float_as_uint(As[base + 4]);
                an[mt][3] = __float_as_uint(As[base + 8 * PAD + 4]);
            }
            #pragma unroll
            for (int nt = 0; nt < 8; nt++)
                bn[nt] = *(float2*)&Wf[(((cg * 8 + nt) * 16 + kt + 1) * 32 + lane) * 2];
        }
        #pragma unroll
        for (int nt = 0; nt < 8; nt++) {
            uint32_t b0 = __float_as_uint(b[nt].x);
            uint32_t b1 = __float_as_uint(b[nt].y);
            mma_tf32(acc[0][nt], a[0][0], a[0][1], a[0][2], a[0][3], b0, b1);
            mma_tf32(acc[1][nt], a[1][0], a[1][1], a[1][2], a[1][3], b0, b1);
        }
        if (kt < 15) {
            #pragma unroll
            for (int mt = 0; mt < 2; mt++)
                #pragma unroll
                for (int q = 0; q < 4; q++) a[mt][q] = an[mt][q];
            #pragma unroll
            for (int nt = 0; nt < 8; nt++) b[nt] = bn[nt];
        }
    }

    // epilogue: + bias, optional relu, scatter via row ids
    #pragma unroll
    for (int mt = 0; mt < 2; mt++) {
        int lrow = rg * 32 + mt * 16 + row_l;
        int r0 = Rid[lrow];
        int r8 = Rid[lrow + 8];
        #pragma unroll
        for (int nt = 0; nt < 8; nt++) {
            int col = cg * 64 + nt * 8 + 2 * kq;
            float2 bb = *(const float2*)&bias[col];
            float2 v0 = make_float2(acc[mt][nt].x + bb.x, acc[mt][nt].y + bb.y);
            float2 v1 = make_float2(acc[mt][nt].z + bb.x, acc[mt][nt].w + bb.y);
            if (do_relu) {
                v0.x = fmaxf(v0.x, 0.f); v0.y = fmaxf(v0.y, 0.f);
                v1.x = fmaxf(v1.x, 0.f); v1.y = fmaxf(v1.y, 0.f);
            }
            if (r0 >= 0) *(float2*)&O[(size_t)r0 * HD + col] = v0;
            if (r8 >= 0) *(float2*)&O[(size_t)r8 * HD + col] = v1;
        }
    }
}

// ---------------- pooling + MLP head (dense 1000-row input) ----------------
__global__ void k_pool(const float* __restrict__ x,
                       const float* __restrict__ l1w,
                       const float* __restrict__ l1b,
                       const float* __restrict__ l2w,
                       const float* __restrict__ l2b,
                       float* __restrict__ out) {
    __shared__ float h[HD];
    __shared__ float red[4];
    int g = blockIdx.x, t = threadIdx.x;
    long long n0 = (long long)g * 2;     // dense rows 2g, 2g+1
    h[t] = tf32r(x[n0 * HD + t] * x[(n0 + 1) * HD + t]);
    __syncthreads();
    float acc = l1b[t];
    #pragma unroll 16
    for (int i = 0; i < HD; i++) acc += h[i] * tf32r(l1w[i * HD + t]);
    acc = fmaxf(acc, 0.f);
    float p = tf32r(acc) * tf32r(l2w[t]);
    #pragma unroll
    for (int o = 16; o; o >>= 1) p += __shfl_xor_sync(0xffffffffu, p, o);
    if ((t & 31) == 0) red[t >> 5] = p;
    __syncthreads();
    if (t == 0) out[g] = red[0] + red[1] + red[2] + red[3] + l2b[0];
}

// ---------------- launch ----------------
extern "C" void kernel_launch(void* const* d_in, const int* in_sizes, int n_in,
                              void* d_out, int out_size) {
    const int*           z    = (const int*)d_in[0];
    const int*           ei   = (const int*)d_in[1];
    const unsigned char* mask = (const unsigned char*)d_in[3];
    const float* zt  = (const float*)d_in[4];
    const float* W0  = (const float*)d_in[5];
    const float* b0  = (const float*)d_in[6];
    const float* W1  = (const float*)d_in[7];
    const float* b1  = (const float*)d_in[8];
    const float* W2  = (const float*)d_in[9];
    const float* b2  = (const float*)d_in[10];
    const float* l1w = (const float*)d_in[11];
    const float* l1b = (const float*)d_in[12];
    const float* l2w = (const float*)d_in[13];
    const float* l2b = (const float*)d_in[14];
    float* out = (float*)d_out;

    const int* src = ei;
    const int* dst = ei + NE;

    float *py = nullptr, *px2 = nullptr, *pxw = nullptr;
    int *pl1 = nullptr, *pl2 = nullptr, *plen1 = nullptr, *plen2 = nullptr;
    cudaGetSymbolAddress((void**)&py, g_y);
    cudaGetSymbolAddress((void**)&px2, g_x2);
    cudaGetSymbolAddress((void**)&pxw, g_xw);
    cudaGetSymbolAddress((void**)&pl1, g_list1);
    cudaGetSymbolAddress((void**)&pl2, g_list2);
    cudaGetSymbolAddress((void**)&plen1, g_len1);
    cudaGetSymbolAddress((void**)&plen2, g_len2);

    const int GEMM_SMEM = (GROWS * PAD + 16384) * sizeof(float)
                          + GROWS * sizeof(int);              // 133,632 B
    cudaFuncSetAttribute(k_gemm_tc,
                         cudaFuncAttributeMaxDynamicSharedMemorySize,
                         GEMM_SMEM);

    // CSR + dinv + dependency lists
    k_zero<<<(NN + 255) / 256, 256>>>();
    k_detect<<<1, 256>>>(mask);
    k_count<<<(NE + 255) / 256, 256>>>(dst, mask);
    k_scan1<<<NBLK, SCAN_B>>>();
    k_scan2<<<1, 128>>>();
    k_scan3<<<(NN + 255) / 256, 256>>>();
    k_fill<<<(NE + 255) / 256, 256>>>(src, dst, mask);
    k_expand0<<<4, 256>>>();
    k_len1<<<1, 1>>>();
    k_expand1<<<CAP2 / 256, 256>>>();
    kw_pack<<<3, 256>>>(W0, W1, W2);

    // layer 0: agg(embeddings) at S1 -> GEMM(W0)+b0+relu -> y at S1 rows
    k_agg<<<CAP1 * 32 / 512, 512>>>(nullptr, z, zt, pxw, pl1, plen1, CAP1, 0);
    k_gemm_tc<<<CAP1 / GROWS, 256, GEMM_SMEM>>>(pxw, py, b0, 1, 0,
                                                pl1, plen1, CAP1, 0);
    // layer 1: agg(y) at S2 -> GEMM(W1)+b1+relu -> x2 at S2 rows
    k_agg<<<CAP2 * 32 / 512, 512>>>(py, nullptr, nullptr, pxw, pl2, plen2, CAP2, 0);
    k_gemm_tc<<<CAP2 / GROWS, 256, GEMM_SMEM>>>(pxw, px2, b1, 0x7FFFFFFF ? 1 : 1, 1,
                                                pl2, plen2, CAP2, 0);
    // layer 2: agg(x2) at centers (dense 1000 rows) -> GEMM(W2)+b2 -> y dense
    k_agg<<<(1000 * 32 + 511) / 512, 512>>>(px2, nullptr, nullptr, pxw,
                                            nullptr, nullptr, 0, 1);
    k_gemm_tc<<<(1000 + GROWS - 1) / GROWS, 256, GEMM_SMEM>>>(
        pxw, py, b2, 0, 2, nullptr, nullptr, 0, 1000);

    // pool + MLP
    k_pool<<<NG, HD>>>(py, l1w, l1b, l2w, l2b, out);
}

// round 9
// speedup vs baseline: 4.3945x; 1.0109x over previous
#include <cuda_runtime.h>
#include <cstdint>

#define NN 100000
#define NE 800000
#define HD 128
#define NG 500
#define SCAN_B 1024
#define NBLK ((NN + SCAN_B - 1) / SCAN_B)   // 98
#define PAD 132                              // A-tile row stride (floats)
#define GROWS 128                            // rows per layer block
#define CAP2 8192                            // list2 capacity (S2, unique)
#define CAP1 65536                           // list1 capacity (S1, unique)

// ---------------- scratch (device globals; no allocation) ----------------
__device__ float g_y [NN * HD];   // layer-0 output (S1 rows) / dense head out
__device__ float g_x2[NN * HD];   // layer-1 output (S2 rows)
__device__ float g_wf[3 * 16384]; // pre-packed W B-fragments (3 layers)
__device__ float g_dinv[NN];
__device__ int   g_cnt[NN];
__device__ int   g_rowptr[NN + 1];
__device__ int   g_cursor[NN];
__device__ int   g_csr[NE];       // src node per (dst-sorted) live edge
__device__ int   g_bsum[128];
__device__ int   g_mask_i32;      // 1 if edge_mask serialized as int32
__device__ unsigned g_flag[(NN + 31) / 32];  // membership bitmap (dedupe)
__device__ int   g_list1[CAP1];   // S1 = S2 + in-neighbors(S2), unique
__device__ int   g_list2[CAP2];   // S2 = centers + in-neighbors(centers), unique
__device__ int   g_len2;          // list2 append cursor (starts at 1000)
__device__ int   g_extra1;        // list1 extra appends beyond len2

// TF32 round (matches GPU tf32 matmul operand rounding)
__device__ __forceinline__ float tf32r(float x) {
    float r;
    asm("cvt.rna.tf32.f32 %0, %1;" : "=f"(r) : "f"(x));
    return r;
}
__device__ __forceinline__ float4 tf32r4(float4 v) {
    return make_float4(tf32r(v.x), tf32r(v.y), tf32r(v.z), tf32r(v.w));
}

__device__ __forceinline__ void mma_tf32(float4& c,
    uint32_t a0, uint32_t a1, uint32_t a2, uint32_t a3,
    uint32_t b0, uint32_t b1) {
    asm volatile(
        "mma.sync.aligned.m16n8k8.row.col.f32.tf32.tf32.f32 "
        "{%0,%1,%2,%3}, {%4,%5,%6,%7}, {%8,%9}, {%0,%1,%2,%3};"
        : "+f"(c.x), "+f"(c.y), "+f"(c.z), "+f"(c.w)
        : "r"(a0), "r"(a1), "r"(a2), "r"(a3), "r"(b0), "r"(b1));
}

// ---------------- init: zero counters/flags + mask sniff + cursors ----------
__global__ void k_init(const unsigned char* __restrict__ m) {
    int i = blockIdx.x * blockDim.x + threadIdx.x;
    if (i < NN) g_cnt[i] = 0;
    if (i < (NN + 31) / 32) g_flag[i] = 0u;
    if (blockIdx.x == 0) {
        __shared__ int any;
        if (threadIdx.x == 0) any = 0;
        __syncthreads();
        int local = 0;
        for (int q = threadIdx.x; q < 65536; q += blockDim.x)
            if ((q & 3) && m[q]) local = 1;
        if (local) any = 1;              // benign race
        __syncthreads();
        if (threadIdx.x == 0) {
            g_mask_i32 = (any == 0);
            g_len2 = 1000;
            g_extra1 = 0;
        }
    }
}

// ---------------- CSR build (4 edges / thread) ----------------
__global__ void k_count(const int* __restrict__ dst,
                        const unsigned char* __restrict__ mask) {
    int i = blockIdx.x * blockDim.x + threadIdx.x;
    if (i >= NE / 4) return;
    int4 d = ((const int4*)dst)[i];
    unsigned m0, m1, m2, m3;
    if (g_mask_i32) {
        int4 mm = ((const int4*)mask)[i];
        m0 = mm.x; m1 = mm.y; m2 = mm.z; m3 = mm.w;
    } else {
        unsigned mm = ((const unsigned*)mask)[i];
        m0 = mm & 0xffu; m1 = mm & 0xff00u;
        m2 = mm & 0xff0000u; m3 = mm & 0xff000000u;
    }
    if (m0) atomicAdd(&g_cnt[d.x], 1);
    if (m1) atomicAdd(&g_cnt[d.y], 1);
    if (m2) atomicAdd(&g_cnt[d.z], 1);
    if (m3) atomicAdd(&g_cnt[d.w], 1);
}

// warp-shuffle block scan; also emits dinv = rsqrt(cnt+1)
__global__ void k_scan1() {
    __shared__ int wsum[32];
    int i = blockIdx.x * SCAN_B + threadIdx.x;
    int v = (i < NN) ? g_cnt[i] : 0;
    if (i < NN) g_dinv[i] = rsqrtf((float)v + 1.0f);
    int lane = threadIdx.x & 31, wid = threadIdx.x >> 5;
    int x = v;
    #pragma unroll
    for (int o = 1; o < 32; o <<= 1) {
        int y = __shfl_up_sync(~0u, x, o);
        if (lane >= o) x += y;
    }
    if (lane == 31) wsum[wid] = x;
    __syncthreads();
    if (wid == 0) {
        int s = wsum[lane];
        #pragma unroll
        for (int o = 1; o < 32; o <<= 1) {
            int y = __shfl_up_sync(~0u, s, o);
            if (lane >= o) s += y;
        }
        wsum[lane] = s;
    }
    __syncthreads();
    int incl = x + (wid ? wsum[wid - 1] : 0);
    if (i < NN) g_rowptr[i] = incl - v;           // exclusive
    if (threadIdx.x == SCAN_B - 1) g_bsum[blockIdx.x] = incl;
}

__global__ void k_scan2() {   // 98 block sums, 1 block of 128
    __shared__ int s[128];
    int t = threadIdx.x;
    int v = (t < NBLK) ? g_bsum[t] : 0;
    s[t] = v;
    __syncthreads();
    for (int off = 1; off < 128; off <<= 1) {
        int tt = (t >= off) ? s[t - off] : 0;
        __syncthreads();
        s[t] += tt;
        __syncthreads();
    }
    if (t < NBLK) g_bsum[t] = s[t] - v;
    if (t == NBLK - 1) g_rowptr[NN] = s[t];
}

// finalize rowptr/cursor; plant centers into list2 + flags
__global__ void k_scan3() {
    int i = blockIdx.x * blockDim.x + threadIdx.x;
    if (i >= NN) return;
    int r = g_rowptr[i] + g_bsum[i / SCAN_B];
    g_rowptr[i] = r;
    g_cursor[i] = r;
    int m = i % 200;
    if (m < 2) {
        g_list2[(i / 200) * 2 + m] = i;
        atomicOr(&g_flag[i >> 5], 1u << (i & 31));
    }
}

__global__ void k_fill(const int* __restrict__ src,
                       const int* __restrict__ dst,
                       const unsigned char* __restrict__ mask) {
    int i = blockIdx.x * blockDim.x + threadIdx.x;
    if (i >= NE / 4) return;
    int4 d = ((const int4*)dst)[i];
    int4 sc = ((const int4*)src)[i];
    unsigned m0, m1, m2, m3;
    if (g_mask_i32) {
        int4 mm = ((const int4*)mask)[i];
        m0 = mm.x; m1 = mm.y; m2 = mm.z; m3 = mm.w;
    } else {
        unsigned mm = ((const unsigned*)mask)[i];
        m0 = mm & 0xffu; m1 = mm & 0xff00u;
        m2 = mm & 0xff0000u; m3 = mm & 0xff000000u;
    }
    if (m0) g_csr[atomicAdd(&g_cursor[d.x], 1)] = sc.x;
    if (m1) g_csr[atomicAdd(&g_cursor[d.y], 1)] = sc.y;
    if (m2) g_csr[atomicAdd(&g_cursor[d.z], 1)] = sc.z;
    if (m3) g_csr[atomicAdd(&g_cursor[d.w], 1)] = sc.w;
}

// ---------------- dependency-set expansion (deduped) ----------------
__global__ void k_expand0() {   // neighbors of centers -> list2
    int i = blockIdx.x * blockDim.x + threadIdx.x;
    if (i >= 1000) return;
    int n = (i >> 1) * 200 + (i & 1);
    int e0 = g_rowptr[n], e1 = g_rowptr[n + 1];
    for (int e = e0; e < e1; e++) {
        int j = g_csr[e];
        unsigned bit = 1u << (j & 31);
        unsigned old = atomicOr(&g_flag[j >> 5], bit);
        if (!(old & bit)) {
            int pos = atomicAdd(&g_len2, 1);
            if (pos < CAP2) g_list2[pos] = j;
        }
    }
}

__global__ void k_expand1() {   // list1 = list2 + neighbors(list2)
    int i = blockIdx.x * blockDim.x + threadIdx.x;
    int len2 = min(g_len2, CAP2);
    if (i >= len2) return;
    int n = g_list2[i];
    g_list1[i] = n;
    int e0 = g_rowptr[n], e1 = g_rowptr[n + 1];
    for (int e = e0; e < e1; e++) {
        int j = g_csr[e];
        unsigned bit = 1u << (j & 31);
        unsigned old = atomicOr(&g_flag[j >> 5], bit);
        if (!(old & bit)) {
            int pos = len2 + atomicAdd(&g_extra1, 1);
            if (pos < CAP1) g_list1[pos] = j;
        }
    }
}

// ---------------- W fragment packing ----------------
__global__ void kw_pack(const float* __restrict__ W0,
                        const float* __restrict__ W1,
                        const float* __restrict__ W2) {
    const float* W = (blockIdx.x == 0) ? W0 : (blockIdx.x == 1) ? W1 : W2;
    float2* out = (float2*)(g_wf + blockIdx.x * 16384);
    for (int idx = threadIdx.x; idx < 8192; idx += blockDim.x) {
        int lane = idx & 31, kt = (idx >> 5) & 15, nt = idx >> 9;
        int k = kt * 8 + (lane & 3);
        int n = nt * 8 + (lane >> 2);
        out[idx] = make_float2(tf32r(W[k * HD + n]), tf32r(W[(k + 4) * HD + n]));
    }
}

// ---------------- fused layer: aggregate -> tf32 MMA -> bias/relu -------------
// 512 threads / 16 warps. Agg phase: warp per row (8 rows/warp). MMA phase:
// 8 row-groups x 2 col-groups, warp tile 16x64, K=128 in 16 k8 steps.
// lenmode: 0 -> dense_len rows; 1 -> len2 (list); 2 -> len2+extra1 (list).
__global__ __launch_bounds__(512)
void k_layer(const float* __restrict__ feat,
             const int* __restrict__ z,
             const float* __restrict__ zt,
             float* __restrict__ O,
             const float* __restrict__ bias,
             int do_relu, int layer,
             const int* __restrict__ list,
             int lenmode, int dense_len, int centers) {
    extern __shared__ float sm[];
    float* As = sm;                       // GROWS x PAD
    float* Wf = sm + GROWS * PAD;         // 16384
    int*   Rid = (int*)(Wf + 16384);      // output rows
    int*   Nid = Rid + GROWS;             // aggregation node ids

    int len = dense_len;
    if (lenmode == 1) len = min(g_len2, CAP2);
    else if (lenmode == 2) len = min(min(g_len2, CAP2) + g_extra1, CAP1);
    int rb = blockIdx.x * GROWS;
    if (rb >= len) return;

    int t = threadIdx.x;
    if (t < GROWS) {
        int li = rb + t;
        int node = -1, orow = -1;
        if (li < len) {
            if (centers) { node = (li >> 1) * 200 + (li & 1); orow = li; }
            else         { node = list[li]; orow = node; }
        }
        Rid[t] = orow;
        Nid[t] = node;
    }
    __syncthreads();

    // stage packed W
    const float4* wsrc = (const float4*)(g_wf + layer * 16384);
    for (int i = t; i < 4096; i += 512) ((float4*)Wf)[i] = wsrc[i];

    // aggregation phase: warp per row
    int wid = t >> 5, lane = t & 31;
    const float4* zt4 = (const float4*)zt;
    const float4* f4  = (const float4*)feat;
    for (int r = wid; r < GROWS; r += 16) {
        int node = Nid[r];
        float4 acc = make_float4(0.f, 0.f, 0.f, 0.f);
        if (node >= 0) {
            float s = g_dinv[node];
            float ss = s * s;
            float4 a = z ? tf32r4(zt4[(size_t)z[node] * 32 + lane])
                         : tf32r4(f4[(size_t)node * 32 + lane]);
            acc = make_float4(ss * a.x, ss * a.y, ss * a.z, ss * a.w);
            int e0 = g_rowptr[node], e1 = g_rowptr[node + 1];
            for (int e = e0; e < e1; e++) {
                int j = g_csr[e];
                float c = s * g_dinv[j];
                float4 v = z ? tf32r4(zt4[(size_t)z[j] * 32 + lane])
                             : tf32r4(f4[(size_t)j * 32 + lane]);
                acc.x += c * v.x; acc.y += c * v.y;
                acc.z += c * v.z; acc.w += c * v.w;
            }
        }
        *(float4*)&As[r * PAD + lane * 4] = tf32r4(acc);
    }
    __syncthreads();

    // MMA phase
    int rg = wid & 7;          // 8 row groups x 16 rows
    int cg = wid >> 3;         // 2 col groups x 64 cols
    int row_l = lane >> 2;
    int kq = lane & 3;

    float4 acc[8];
    #pragma unroll
    for (int nt = 0; nt < 8; nt++) acc[nt] = make_float4(0.f, 0.f, 0.f, 0.f);

    uint32_t a[4];
    float2   b[8];
    {
        int base = (rg * 16 + row_l) * PAD + kq;
        a[0] = __float_as_uint(As[base]);
        a[1] = __float_as_uint(As[base + 8 * PAD]);
        a[2] = __float_as_uint(As[base + 4]);
        a[3] = __float_as_uint(As[base + 8 * PAD + 4]);
    }
    #pragma unroll
    for (int nt = 0; nt < 8; nt++)
        b[nt] = *(float2*)&Wf[(((cg * 8 + nt) * 16) * 32 + lane) * 2];

    #pragma unroll
    for (int kt = 0; kt < 16; kt++) {
        uint32_t an[4];
        float2   bn[8];
        if (kt < 15) {
            int base = (rg * 16 + row_l) * PAD + (kt + 1) * 8 + kq;
            an[0] = __float_as_uint(As[base]);
            an[1] = __float_as_uint(As[base + 8 * PAD]);
            an[2] = __float_as_uint(As[base + 4]);
            an[3] = __float_as_uint(As[base + 8 * PAD + 4]);
            #pragma unroll
            for (int nt = 0; nt < 8; nt++)
                bn[nt] = *(float2*)&Wf[(((cg * 8 + nt) * 16 + kt + 1) * 32 + lane) * 2];
        }
        #pragma unroll
        for (int nt = 0; nt < 8; nt++)
            mma_tf32(acc[nt], a[0], a[1], a[2], a[3],
                     __float_as_uint(b[nt].x), __float_as_uint(b[nt].y));
        if (kt < 15) {
            #pragma unroll
            for (int q = 0; q < 4; q++) a[q] = an[q];
            #pragma unroll
            for (int nt = 0; nt < 8; nt++) b[nt] = bn[nt];
        }
    }

    // epilogue
    int lrow = rg * 16 + row_l;
    int r0 = Rid[lrow];
    int r8 = Rid[lrow + 8];
    #pragma unroll
    for (int nt = 0; nt < 8; nt++) {
        int col = cg * 64 + nt * 8 + 2 * kq;
        float2 bb = *(const float2*)&bias[col];
        float2 v0 = make_float2(acc[nt].x + bb.x, acc[nt].y + bb.y);
        float2 v1 = make_float2(acc[nt].z + bb.x, acc[nt].w + bb.y);
        if (do_relu) {
            v0.x = fmaxf(v0.x, 0.f); v0.y = fmaxf(v0.y, 0.f);
            v1.x = fmaxf(v1.x, 0.f); v1.y = fmaxf(v1.y, 0.f);
        }
        if (r0 >= 0) *(float2*)&O[(size_t)r0 * HD + col] = v0;
        if (r8 >= 0) *(float2*)&O[(size_t)r8 * HD + col] = v1;
    }
}

// ---------------- pooling + MLP head (dense 1000-row input) ----------------
__global__ void k_pool(const float* __restrict__ x,
                       const float* __restrict__ l1w,
                       const float* __restrict__ l1b,
                       const float* __restrict__ l2w,
                       const float* __restrict__ l2b,
                       float* __restrict__ out) {
    __shared__ float h[HD];
    __shared__ float red[4];
    int g = blockIdx.x, t = threadIdx.x;
    long long n0 = (long long)g * 2;
    h[t] = tf32r(x[n0 * HD + t] * x[(n0 + 1) * HD + t]);
    __syncthreads();
    float acc = l1b[t];
    #pragma unroll 16
    for (int i = 0; i < HD; i++) acc += h[i] * tf32r(l1w[i * HD + t]);
    acc = fmaxf(acc, 0.f);
    float p = tf32r(acc) * tf32r(l2w[t]);
    #pragma unroll
    for (int o = 16; o; o >>= 1) p += __shfl_xor_sync(0xffffffffu, p, o);
    if ((t & 31) == 0) red[t >> 5] = p;
    __syncthreads();
    if (t == 0) out[g] = red[0] + red[1] + red[2] + red[3] + l2b[0];
}

// ---------------- launch ----------------
extern "C" void kernel_launch(void* const* d_in, const int* in_sizes, int n_in,
                              void* d_out, int out_size) {
    const int*           z    = (const int*)d_in[0];
    const int*           ei   = (const int*)d_in[1];
    const unsigned char* mask = (const unsigned char*)d_in[3];
    const float* zt  = (const float*)d_in[4];
    const float* W0  = (const float*)d_in[5];
    const float* b0  = (const float*)d_in[6];
    const float* W1  = (const float*)d_in[7];
    const float* b1  = (const float*)d_in[8];
    const float* W2  = (const float*)d_in[9];
    const float* b2  = (const float*)d_in[10];
    const float* l1w = (const float*)d_in[11];
    const float* l1b = (const float*)d_in[12];
    const float* l2w = (const float*)d_in[13];
    const float* l2b = (const float*)d_in[14];
    float* out = (float*)d_out;

    const int* src = ei;
    const int* dst = ei + NE;

    float *py = nullptr, *px2 = nullptr;
    int *pl1 = nullptr, *pl2 = nullptr;
    cudaGetSymbolAddress((void**)&py, g_y);
    cudaGetSymbolAddress((void**)&px2, g_x2);
    cudaGetSymbolAddress((void**)&pl1, g_list1);
    cudaGetSymbolAddress((void**)&pl2, g_list2);

    const int LAYER_SMEM = (GROWS * PAD + 16384) * sizeof(float)
                           + 2 * GROWS * sizeof(int);          // 134,656 B
    cudaFuncSetAttribute(k_layer,
                         cudaFuncAttributeMaxDynamicSharedMemorySize,
                         LAYER_SMEM);

    // CSR + dinv + dependency lists
    k_init<<<(NN + 255) / 256, 256>>>(mask);
    k_count<<<(NE / 4 + 255) / 256, 256>>>(dst, mask);
    k_scan1<<<NBLK, SCAN_B>>>();
    k_scan2<<<1, 128>>>();
    k_scan3<<<(NN + 255) / 256, 256>>>();
    k_fill<<<(NE / 4 + 255) / 256, 256>>>(src, dst, mask);
    k_expand0<<<4, 256>>>();
    k_expand1<<<CAP2 / 256, 256>>>();
    kw_pack<<<3, 256>>>(W0, W1, W2);

    // layer 0: agg(zt[z]) + GEMM(W0)+b0+relu -> y at S1 rows
    k_layer<<<CAP1 / GROWS, 512, LAYER_SMEM>>>(
        nullptr, z, zt, py, b0, 1, 0, pl1, 2, 0, 0);
    // layer 1: agg(y) + GEMM(W1)+b1+relu -> x2 at S2 rows
    k_layer<<<CAP2 / GROWS, 512, LAYER_SMEM>>>(
        py, nullptr, nullptr, px2, b1, 1, 1, pl2, 1, 0, 0);
    // layer 2: agg(x2) at centers + GEMM(W2)+b2 -> y dense rows 0..999
    k_layer<<<(1000 + GROWS - 1) / GROWS, 512, LAYER_SMEM>>>(
        px2, nullptr, nullptr, py, b2, 0, 2, nullptr, 0, 1000, 1);

    // pool + MLP
    k_pool<<<NG, HD>>>(py, l1w, l1b, l2w, l2b, out);
}